// round 5
// baseline (speedup 1.0000x reference)
#include <cuda_runtime.h>
#include <cstdint>

#define NB 8
#define NS 1024
#define NE 768
#define NH 12
#define ND 64
#define NT (NB*NS)   // 8192 tokens

// Scratch (device globals: allocation-free rule)
__device__ float g_q[NB*NH*NS*ND];     // [B,H,S,D]
__device__ float g_k[NB*NH*NS*ND];
__device__ float g_v[NB*NH*NS*ND];
__device__ float g_attn[NT*NE];        // [B,S,E] concat layout

// ---------------------------------------------------------------------------
__device__ __forceinline__ uint32_t f2tf(float f) {
    uint32_t r;
    asm("cvt.rna.tf32.f32 %0, %1;" : "=r"(r) : "f"(f));
    return r;
}
__device__ __forceinline__ void mma_tf32(float* d, const uint32_t* a, const uint32_t* b) {
    asm volatile(
        "mma.sync.aligned.m16n8k8.row.col.f32.tf32.tf32.f32 "
        "{%0,%1,%2,%3}, {%4,%5,%6,%7}, {%8,%9}, {%0,%1,%2,%3};"
        : "+f"(d[0]), "+f"(d[1]), "+f"(d[2]), "+f"(d[3])
        : "r"(a[0]), "r"(a[1]), "r"(a[2]), "r"(a[3]), "r"(b[0]), "r"(b[1]));
}
__device__ __forceinline__ uint32_t smem_u32(const void* p) {
    uint32_t a;
    asm("{ .reg .u64 t; cvta.to.shared.u64 t, %1; cvt.u32.u64 %0, t; }"
        : "=r"(a) : "l"(p));
    return a;
}
__device__ __forceinline__ void cp16(uint32_t dst, const void* src) {
    asm volatile("cp.async.cg.shared.global [%0], [%1], 16;"
                 :: "r"(dst), "l"(src) : "memory");
}
#define CP_COMMIT() asm volatile("cp.async.commit_group;" ::: "memory")
#define CP_WAIT(n)  asm volatile("cp.async.wait_group %0;" :: "n"(n) : "memory")

// ---------------------------------------------------------------------------
// GEMM v3: D[8192 x 768] = A @ W + bias. BM=128 BN=64 BK=32, double-buffered,
// register-prefetched, 2 CTAs/SM (regs capped at 128). 8 warps = 4m x 2n,
// warp tile 32x32 -> 32 accumulators/thread.
// mode 0: z picks Wq/Wk/Wv -> g_q/g_k/g_v split-head. mode 1: Wo -> Dext.
// ---------------------------------------------------------------------------
#define GASTR 36
#define GBSTR 72
#define GEMM_SMEM ((2*128*GASTR + 2*32*GBSTR) * 4)   // 55296 B

__global__ __launch_bounds__(256, 2) void gemm_kernel(
    const float* __restrict__ Ain,
    const float* __restrict__ W0, const float* __restrict__ W1,
    const float* __restrict__ W2,
    const float* __restrict__ bq_, const float* __restrict__ bk_,
    const float* __restrict__ bv_,
    float* __restrict__ Dext, int mode)
{
    extern __shared__ uint32_t gsm[];
    uint32_t* As = gsm;                    // [2][128*GASTR]
    uint32_t* Bs = gsm + 2*128*GASTR;      // [2][32*GBSTR]

    const int z = blockIdx.z;
    const float* W    = (mode == 1) ? W0  : (z == 0 ? W0  : z == 1 ? W1  : W2);
    const float* bias = (mode == 1) ? bq_ : (z == 0 ? bq_ : z == 1 ? bk_ : bv_);
    float* D = (mode == 1) ? Dext : (z == 0 ? g_q : z == 1 ? g_k : g_v);
    const float* A = Ain ? Ain : g_attn;

    const int tid = threadIdx.x, wid = tid >> 5, lane = tid & 31;
    const int gid = lane >> 2, tig = lane & 3;
    const int wm = wid >> 1, wn = wid & 1;
    const int m0 = blockIdx.x * 128, n0 = blockIdx.y * 64;

    // staging indices: A 128x32 (4 float4/thread), B 32x64 (2 float4/thread)
    int ar[4], ac[4], brr[2], bcc[2];
    #pragma unroll
    for (int i = 0; i < 4; i++) {
        int idx = tid + i * 256;
        ar[i] = idx >> 3;  ac[i] = (idx & 7) * 4;
    }
    #pragma unroll
    for (int i = 0; i < 2; i++) {
        int idx = tid + i * 256;
        brr[i] = idx >> 4; bcc[i] = (idx & 15) * 4;
    }

    float4 pa[4], pb[2];
    #pragma unroll
    for (int i = 0; i < 4; i++)
        pa[i] = *(const float4*)(A + (size_t)(m0 + ar[i]) * NE + ac[i]);
    #pragma unroll
    for (int i = 0; i < 2; i++)
        pb[i] = *(const float4*)(W + (size_t)brr[i] * NE + n0 + bcc[i]);
    #pragma unroll
    for (int i = 0; i < 4; i++) {
        uint4 va = { f2tf(pa[i].x), f2tf(pa[i].y), f2tf(pa[i].z), f2tf(pa[i].w) };
        *(uint4*)(&As[ar[i] * GASTR + ac[i]]) = va;
    }
    #pragma unroll
    for (int i = 0; i < 2; i++) {
        uint4 vb = { f2tf(pb[i].x), f2tf(pb[i].y), f2tf(pb[i].z), f2tf(pb[i].w) };
        *(uint4*)(&Bs[brr[i] * GBSTR + bcc[i]]) = vb;
    }

    float c[2][4][4] = {};

    #pragma unroll 1
    for (int kb = 0; kb < 24; kb++) {
        __syncthreads();
        const int cur = kb & 1, nxt = cur ^ 1;
        if (kb < 23) {
            const int k0n = (kb + 1) * 32;
            #pragma unroll
            for (int i = 0; i < 4; i++)
                pa[i] = *(const float4*)(A + (size_t)(m0 + ar[i]) * NE + k0n + ac[i]);
            #pragma unroll
            for (int i = 0; i < 2; i++)
                pb[i] = *(const float4*)(W + (size_t)(k0n + brr[i]) * NE + n0 + bcc[i]);
        }
        const uint32_t* Ab = As + cur * 128 * GASTR;
        const uint32_t* Bb = Bs + cur * 32 * GBSTR;
        #pragma unroll
        for (int kk = 0; kk < 4; kk++) {
            uint32_t a[2][4];
            #pragma unroll
            for (int mi = 0; mi < 2; mi++) {
                const int mr = wm * 32 + mi * 16;
                a[mi][0] = Ab[(mr + gid    ) * GASTR + kk * 8 + tig    ];
                a[mi][1] = Ab[(mr + gid + 8) * GASTR + kk * 8 + tig    ];
                a[mi][2] = Ab[(mr + gid    ) * GASTR + kk * 8 + tig + 4];
                a[mi][3] = Ab[(mr + gid + 8) * GASTR + kk * 8 + tig + 4];
            }
            #pragma unroll
            for (int nt = 0; nt < 4; nt++) {
                uint32_t b[2];
                const int nc = wn * 32 + nt * 8 + gid;
                b[0] = Bb[(kk * 8 + tig    ) * GBSTR + nc];
                b[1] = Bb[(kk * 8 + tig + 4) * GBSTR + nc];
                mma_tf32(c[0][nt], a[0], b);
                mma_tf32(c[1][nt], a[1], b);
            }
        }
        if (kb < 23) {
            uint32_t* An = As + nxt * 128 * GASTR;
            uint32_t* Bn = Bs + nxt * 32 * GBSTR;
            #pragma unroll
            for (int i = 0; i < 4; i++) {
                uint4 va = { f2tf(pa[i].x), f2tf(pa[i].y), f2tf(pa[i].z), f2tf(pa[i].w) };
                *(uint4*)(&An[ar[i] * GASTR + ac[i]]) = va;
            }
            #pragma unroll
            for (int i = 0; i < 2; i++) {
                uint4 vb = { f2tf(pb[i].x), f2tf(pb[i].y), f2tf(pb[i].z), f2tf(pb[i].w) };
                *(uint4*)(&Bn[brr[i] * GBSTR + bcc[i]]) = vb;
            }
        }
    }

    #pragma unroll
    for (int mi = 0; mi < 2; mi++) {
        const int r0 = m0 + wm * 32 + mi * 16 + gid;
        #pragma unroll
        for (int nt = 0; nt < 4; nt++) {
            const int n = n0 + wn * 32 + nt * 8 + 2 * tig;
            const float bx = bias[n], by = bias[n + 1];
            float2 lo = { c[mi][nt][0] + bx, c[mi][nt][1] + by };
            float2 hi = { c[mi][nt][2] + bx, c[mi][nt][3] + by };
            if (mode == 0) {
                const int h = n >> 6, d = n & 63;
                const int b0_ = r0 >> 10, s0 = r0 & 1023;
                const int b1_ = (r0 + 8) >> 10, s1 = (r0 + 8) & 1023;
                *(float2*)(D + (((size_t)b0_ * NH + h) * NS + s0) * ND + d) = lo;
                *(float2*)(D + (((size_t)b1_ * NH + h) * NS + s1) * ND + d) = hi;
            } else {
                *(float2*)(D + (size_t)r0 * NE + n) = lo;
                *(float2*)(D + (size_t)(r0 + 8) * NE + n) = hi;
            }
        }
    }
}

// ---------------------------------------------------------------------------
// Flash attention v2 (unchanged from R4). grid=(8, 96), 128 threads (4 warps).
// ---------------------------------------------------------------------------
#define QPS 68
#define KSR 68
#define VSR 72
#define OFF_K  (128*QPS)            // words
#define OFF_V  (OFF_K + 2*64*KSR)
#define FLASH_SMEM ((OFF_V + 64*VSR) * 4)   // 88064 B

__global__ __launch_bounds__(128) void flash_kernel()
{
    extern __shared__ float fsm[];
    float* QP = fsm;
    float* Kb = fsm + OFF_K;
    float* Vb = fsm + OFF_V;
    uint32_t* QPu = (uint32_t*)QP;
    const uint32_t qp_b = smem_u32(QP);
    const uint32_t k_b  = smem_u32(Kb);
    const uint32_t v_b  = smem_u32(Vb);

    const int qt = blockIdx.x, bh = blockIdx.y;
    const float* Qg = g_q + (size_t)bh * NS * ND + qt * 128 * ND;
    const float* Kg = g_k + (size_t)bh * NS * ND;
    const float* Vg = g_v + (size_t)bh * NS * ND;

    const int tid = threadIdx.x, w = tid >> 5, lane = tid & 31;
    const int gid = lane >> 2, tig = lane & 3;

    #pragma unroll
    for (int i = 0; i < 16; i++) {
        int idx = tid + i * 128, r = idx >> 4, c4 = idx & 15;
        cp16(qp_b + (r * QPS + c4 * 4) * 4, Qg + r * 64 + c4 * 4);
    }
    #pragma unroll
    for (int i = 0; i < 8; i++) {
        int idx = tid + i * 128, r = idx >> 4, c4 = idx & 15;
        cp16(k_b + (r * KSR + c4 * 4) * 4, Kg + r * 64 + c4 * 4);
    }
    CP_COMMIT();
    CP_WAIT(0);
    __syncthreads();

    uint32_t qf[2][8][4];
    #pragma unroll
    for (int h = 0; h < 2; h++) {
        const int r = w * 32 + h * 16 + gid;
        #pragma unroll
        for (int kk = 0; kk < 8; kk++) {
            qf[h][kk][0] = f2tf(0.125f * QP[(r    ) * QPS + kk * 8 + tig    ]);
            qf[h][kk][1] = f2tf(0.125f * QP[(r + 8) * QPS + kk * 8 + tig    ]);
            qf[h][kk][2] = f2tf(0.125f * QP[(r    ) * QPS + kk * 8 + tig + 4]);
            qf[h][kk][3] = f2tf(0.125f * QP[(r + 8) * QPS + kk * 8 + tig + 4]);
        }
    }
    __syncthreads();

    #pragma unroll
    for (int i = 0; i < 8; i++) {
        int idx = tid + i * 128, r = idx >> 4, c4 = idx & 15;
        cp16(v_b + (r * VSR + c4 * 4) * 4, Vg + r * 64 + c4 * 4);
    }
    CP_COMMIT();
    #pragma unroll
    for (int i = 0; i < 8; i++) {
        int idx = tid + i * 128, r = idx >> 4, c4 = idx & 15;
        cp16(k_b + (64 * KSR + r * KSR + c4 * 4) * 4, Kg + (64 + r) * 64 + c4 * 4);
    }
    CP_COMMIT();

    float o[2][8][4] = {};
    float mrow[2][2], lrow[2][2];
    #pragma unroll
    for (int h = 0; h < 2; h++) { mrow[h][0] = mrow[h][1] = -1e30f; lrow[h][0] = lrow[h][1] = 0.f; }

    #pragma unroll 1
    for (int kt = 0; kt < 16; kt++) {
        const float* Kc = Kb + (kt & 1) * 64 * KSR;

        float s[2][8][4] = {};
        #pragma unroll
        for (int kk = 0; kk < 8; kk++) {
            #pragma unroll
            for (int nt = 0; nt < 8; nt++) {
                uint32_t b[2];
                b[0] = f2tf(Kc[(nt * 8 + gid) * KSR + kk * 8 + tig    ]);
                b[1] = f2tf(Kc[(nt * 8 + gid) * KSR + kk * 8 + tig + 4]);
                mma_tf32(s[0][nt], qf[0][kk], b);
                mma_tf32(s[1][nt], qf[1][kk], b);
            }
        }

        #pragma unroll
        for (int h = 0; h < 2; h++) {
            const int r = w * 32 + h * 16 + gid;
            float mx0 = -1e30f, mx1 = -1e30f;
            #pragma unroll
            for (int nt = 0; nt < 8; nt++) {
                mx0 = fmaxf(mx0, fmaxf(s[h][nt][0], s[h][nt][1]));
                mx1 = fmaxf(mx1, fmaxf(s[h][nt][2], s[h][nt][3]));
            }
            #pragma unroll
            for (int off = 1; off < 4; off <<= 1) {
                mx0 = fmaxf(mx0, __shfl_xor_sync(0xffffffffu, mx0, off));
                mx1 = fmaxf(mx1, __shfl_xor_sync(0xffffffffu, mx1, off));
            }
            const float mn0 = fmaxf(mrow[h][0], mx0), mn1 = fmaxf(mrow[h][1], mx1);
            const float al0 = __expf(mrow[h][0] - mn0), al1 = __expf(mrow[h][1] - mn1);
            float rs0 = 0.f, rs1 = 0.f;
            #pragma unroll
            for (int nt = 0; nt < 8; nt++) {
                float p0 = __expf(s[h][nt][0] - mn0);
                float p1 = __expf(s[h][nt][1] - mn0);
                float p2 = __expf(s[h][nt][2] - mn1);
                float p3 = __expf(s[h][nt][3] - mn1);
                rs0 += p0 + p1;  rs1 += p2 + p3;
                const int col = nt * 8 + 2 * tig;
                uint2 w0 = { f2tf(p0), f2tf(p1) };
                uint2 w1 = { f2tf(p2), f2tf(p3) };
                *(uint2*)(&QPu[(r    ) * QPS + col]) = w0;
                *(uint2*)(&QPu[(r + 8) * QPS + col]) = w1;
            }
            #pragma unroll
            for (int off = 1; off < 4; off <<= 1) {
                rs0 += __shfl_xor_sync(0xffffffffu, rs0, off);
                rs1 += __shfl_xor_sync(0xffffffffu, rs1, off);
            }
            lrow[h][0] = lrow[h][0] * al0 + rs0;  mrow[h][0] = mn0;
            lrow[h][1] = lrow[h][1] * al1 + rs1;  mrow[h][1] = mn1;
            #pragma unroll
            for (int nt = 0; nt < 8; nt++) {
                o[h][nt][0] *= al0;  o[h][nt][1] *= al0;
                o[h][nt][2] *= al1;  o[h][nt][3] *= al1;
            }
        }

        if (kt < 15) { CP_WAIT(1); } else { CP_WAIT(0); }
        __syncthreads();

        #pragma unroll
        for (int kk = 0; kk < 8; kk++) {
            uint32_t vb[8][2];
            #pragma unroll
            for (int nt = 0; nt < 8; nt++) {
                vb[nt][0] = f2tf(Vb[(kk * 8 + tig    ) * VSR + nt * 8 + gid]);
                vb[nt][1] = f2tf(Vb[(kk * 8 + tig + 4) * VSR + nt * 8 + gid]);
            }
            #pragma unroll
            for (int h = 0; h < 2; h++) {
                const int r = w * 32 + h * 16 + gid;
                uint32_t a[4];
                a[0] = QPu[(r    ) * QPS + kk * 8 + tig    ];
                a[1] = QPu[(r + 8) * QPS + kk * 8 + tig    ];
                a[2] = QPu[(r    ) * QPS + kk * 8 + tig + 4];
                a[3] = QPu[(r + 8) * QPS + kk * 8 + tig + 4];
                #pragma unroll
                for (int nt = 0; nt < 8; nt++)
                    mma_tf32(o[h][nt], a, vb[nt]);
            }
        }

        if (kt < 15) {
            __syncthreads();
            #pragma unroll
            for (int i = 0; i < 8; i++) {
                int idx = tid + i * 128, r = idx >> 4, c4 = idx & 15;
                cp16(v_b + (r * VSR + c4 * 4) * 4,
                     Vg + (size_t)((kt + 1) * 64 + r) * 64 + c4 * 4);
            }
            CP_COMMIT();
            if (kt < 14) {
                #pragma unroll
                for (int i = 0; i < 8; i++) {
                    int idx = tid + i * 128, r = idx >> 4, c4 = idx & 15;
                    cp16(k_b + ((kt & 1) * 64 * KSR + r * KSR + c4 * 4) * 4,
                         Kg + (size_t)((kt + 2) * 64 + r) * 64 + c4 * 4);
                }
                CP_COMMIT();
                CP_WAIT(2);
            } else {
                CP_WAIT(1);
            }
            __syncthreads();
        }
    }

    const int bb = bh / NH, hh = bh % NH;
    #pragma unroll
    for (int h = 0; h < 2; h++) {
        const float inv0 = 1.0f / lrow[h][0], inv1 = 1.0f / lrow[h][1];
        const int r0 = qt * 128 + w * 32 + h * 16 + gid;
        const int r1 = r0 + 8;
        #pragma unroll
        for (int nt = 0; nt < 8; nt++) {
            const int col = hh * ND + nt * 8 + 2 * tig;
            float2 w0 = { o[h][nt][0] * inv0, o[h][nt][1] * inv0 };
            float2 w1 = { o[h][nt][2] * inv1, o[h][nt][3] * inv1 };
            *(float2*)(g_attn + ((size_t)bb * NS + r0) * NE + col) = w0;
            *(float2*)(g_attn + ((size_t)bb * NS + r1) * NE + col) = w1;
        }
    }
}

// ---------------------------------------------------------------------------
extern "C" void kernel_launch(void* const* d_in, const int* in_sizes, int n_in,
                              void* d_out, int out_size)
{
    const float* X  = (const float*)d_in[0];
    const float* Wq = (const float*)d_in[1];
    const float* bq = (const float*)d_in[2];
    const float* Wk = (const float*)d_in[3];
    const float* bk = (const float*)d_in[4];
    const float* Wv = (const float*)d_in[5];
    const float* bv = (const float*)d_in[6];
    const float* Wo = (const float*)d_in[7];
    const float* bo = (const float*)d_in[8];
    float* out = (float*)d_out;

    cudaFuncSetAttribute(gemm_kernel,
                         cudaFuncAttributeMaxDynamicSharedMemorySize, GEMM_SMEM);
    cudaFuncSetAttribute(flash_kernel,
                         cudaFuncAttributeMaxDynamicSharedMemorySize, FLASH_SMEM);

    gemm_kernel<<<dim3(NT/128, NE/64, 3), 256, GEMM_SMEM>>>(
        X, Wq, Wk, Wv, bq, bk, bv, nullptr, 0);

    flash_kernel<<<dim3(NS/128, NB*NH), 128, FLASH_SMEM>>>();

    gemm_kernel<<<dim3(NT/128, NE/64, 1), 256, GEMM_SMEM>>>(
        nullptr, Wo, Wo, Wo, bo, bo, bo, out, 1);
}

// round 7
// speedup vs baseline: 1.2117x; 1.2117x over previous
#include <cuda_runtime.h>
#include <cstdint>

#define NB 8
#define NS 1024
#define NE 768
#define NH 12
#define ND 64
#define NT (NB*NS)   // 8192 tokens

// Scratch (device globals: allocation-free rule)
__device__ float g_q[NB*NH*NS*ND];     // [B,H,S,D], tf32-rounded, Q pre-scaled
__device__ float g_k[NB*NH*NS*ND];
__device__ float g_v[NB*NH*NS*ND];
__device__ float g_attn[NT*NE];        // [B,S,E], tf32-rounded
__device__ float g_xr[NT*NE];          // tf32-rounded X
__device__ float g_wr[4*NE*NE];        // tf32-rounded Wq,Wk,Wv,Wo

// ---------------------------------------------------------------------------
__device__ __forceinline__ uint32_t f2tf(float f) {
    uint32_t r;
    asm("cvt.rna.tf32.f32 %0, %1;" : "=r"(r) : "f"(f));
    return r;
}
__device__ __forceinline__ void mma_tf32(float* d, const uint32_t* a, const uint32_t* b) {
    asm volatile(
        "mma.sync.aligned.m16n8k8.row.col.f32.tf32.tf32.f32 "
        "{%0,%1,%2,%3}, {%4,%5,%6,%7}, {%8,%9}, {%0,%1,%2,%3};"
        : "+f"(d[0]), "+f"(d[1]), "+f"(d[2]), "+f"(d[3])
        : "r"(a[0]), "r"(a[1]), "r"(a[2]), "r"(a[3]), "r"(b[0]), "r"(b[1]));
}
__device__ __forceinline__ uint32_t smem_u32(const void* p) {
    uint32_t a;
    asm("{ .reg .u64 t; cvta.to.shared.u64 t, %1; cvt.u32.u64 %0, t; }"
        : "=r"(a) : "l"(p));
    return a;
}
__device__ __forceinline__ void cp16(uint32_t dst, const void* src) {
    asm volatile("cp.async.cg.shared.global [%0], [%1], 16;"
                 :: "r"(dst), "l"(src) : "memory");
}
#define CP_COMMIT() asm volatile("cp.async.commit_group;" ::: "memory")
#define CP_WAIT(n)  asm volatile("cp.async.wait_group %0;" :: "n"(n) : "memory")

// ---------------------------------------------------------------------------
// Kernel 0: round X and all weights to tf32 (rna) once.
// ---------------------------------------------------------------------------
#define NX4 (NT*NE/4)      // 1572864
#define NW4 (NE*NE/4)      // 147456

__global__ __launch_bounds__(256) void round_kernel(
    const float* __restrict__ X,
    const float* __restrict__ Wq, const float* __restrict__ Wk,
    const float* __restrict__ Wv, const float* __restrict__ Wo)
{
    int idx = blockIdx.x * 256 + threadIdx.x;
    const float4* src4;
    float4* dst4;
    if (idx < NX4) {
        src4 = (const float4*)X + idx;
        dst4 = (float4*)g_xr + idx;
    } else {
        int j = idx - NX4;
        int w = j / NW4, o = j - w * NW4;
        const float* s = (w == 0) ? Wq : (w == 1) ? Wk : (w == 2) ? Wv : Wo;
        src4 = (const float4*)s + o;
        dst4 = (float4*)(g_wr + (size_t)w * NE * NE) + o;
    }
    float4 v = *src4;
    float4 r;
    r.x = __uint_as_float(f2tf(v.x));
    r.y = __uint_as_float(f2tf(v.y));
    r.z = __uint_as_float(f2tf(v.z));
    r.w = __uint_as_float(f2tf(v.w));
    *dst4 = r;
}

// ---------------------------------------------------------------------------
// GEMM v4: BM=128 BN=128 BK=32, cp.async double-buffered, no cvt in loop,
// 2 CTAs/SM. 8 warps = 4m x 2n, warp tile 32x64.
// mode 0: z picks Wq/Wk/Wv -> g_q/g_k/g_v (tf32-rounded, Q scaled 1/8).
// mode 1: Wo, A = g_attn -> Dext (plain f32 + bias, final output).
// ---------------------------------------------------------------------------
#define GASTR 36
#define GBSTR 136
#define AST (128*GASTR)     // 4608 words per A stage
#define BST (32*GBSTR)      // 4352 words per B stage
#define GEMM_SMEM ((2*AST + 2*BST) * 4)   // 71680 B

__global__ __launch_bounds__(256, 2) void gemm_kernel(
    const float* __restrict__ b0_, const float* __restrict__ b1_,
    const float* __restrict__ b2_,
    float* __restrict__ Dext, int mode)
{
    extern __shared__ uint32_t gsm[];
    uint32_t* As = gsm;                // [2][AST]
    uint32_t* Bs = gsm + 2 * AST;      // [2][BST]
    const uint32_t ua = smem_u32(As);
    const uint32_t ub = smem_u32(Bs);

    const int z = blockIdx.z;
    const float* A = (mode == 0) ? g_xr : g_attn;
    const float* W = g_wr + (size_t)((mode == 0) ? z : 3) * NE * NE;
    const float* bias = (mode == 0) ? (z == 0 ? b0_ : z == 1 ? b1_ : b2_) : b0_;
    float* D = (mode == 0) ? (z == 0 ? g_q : z == 1 ? g_k : g_v) : Dext;
    const float qs = (mode == 0 && z == 0) ? 0.125f : 1.0f;

    const int tid = threadIdx.x, wid = tid >> 5, lane = tid & 31;
    const int gid = lane >> 2, tig = lane & 3;
    const int wm = wid >> 1, wn = wid & 1;
    const int m0 = blockIdx.x * 128, n0 = blockIdx.y * 128;

    // staging: A 128x32 (4 cp16/thread), B 32x128 (4 cp16/thread)
    int ar[4], ac[4], brr[4], bcc[4];
    #pragma unroll
    for (int i = 0; i < 4; i++) {
        int idx = tid + i * 256;
        ar[i] = idx >> 3;  ac[i] = (idx & 7) * 4;
        brr[i] = idx >> 5; bcc[i] = (idx & 31) * 4;
    }

    // prologue: stages 0, 1
    #pragma unroll
    for (int s = 0; s < 2; s++) {
        #pragma unroll
        for (int i = 0; i < 4; i++) {
            cp16(ua + (s * AST + ar[i] * GASTR + ac[i]) * 4,
                 A + (size_t)(m0 + ar[i]) * NE + s * 32 + ac[i]);
            cp16(ub + (s * BST + brr[i] * GBSTR + bcc[i]) * 4,
                 W + (size_t)(s * 32 + brr[i]) * NE + n0 + bcc[i]);
        }
        CP_COMMIT();
    }
    CP_WAIT(1);
    __syncthreads();

    float c[2][8][4] = {};

    #pragma unroll 1
    for (int kb = 0; kb < 24; kb++) {
        const int cur = kb & 1;
        const uint32_t* Ab = As + cur * AST;
        const uint32_t* Bb = Bs + cur * BST;
        #pragma unroll
        for (int kk = 0; kk < 4; kk++) {
            uint32_t a[2][4];
            #pragma unroll
            for (int mi = 0; mi < 2; mi++) {
                const int mr = wm * 32 + mi * 16;
                a[mi][0] = Ab[(mr + gid    ) * GASTR + kk * 8 + tig    ];
                a[mi][1] = Ab[(mr + gid + 8) * GASTR + kk * 8 + tig    ];
                a[mi][2] = Ab[(mr + gid    ) * GASTR + kk * 8 + tig + 4];
                a[mi][3] = Ab[(mr + gid + 8) * GASTR + kk * 8 + tig + 4];
            }
            #pragma unroll
            for (int nt = 0; nt < 8; nt++) {
                uint32_t b[2];
                const int nc = wn * 64 + nt * 8 + gid;
                b[0] = Bb[(kk * 8 + tig    ) * GBSTR + nc];
                b[1] = Bb[(kk * 8 + tig + 4) * GBSTR + nc];
                mma_tf32(c[0][nt], a[0], b);
                mma_tf32(c[1][nt], a[1], b);
            }
        }
        if (kb < 23) {
            __syncthreads();                 // all warps done reading buffer cur
            if (kb < 22) {
                const int kn = kb + 2;
                #pragma unroll
                for (int i = 0; i < 4; i++) {
                    cp16(ua + (cur * AST + ar[i] * GASTR + ac[i]) * 4,
                         A + (size_t)(m0 + ar[i]) * NE + kn * 32 + ac[i]);
                    cp16(ub + (cur * BST + brr[i] * GBSTR + bcc[i]) * 4,
                         W + (size_t)(kn * 32 + brr[i]) * NE + n0 + bcc[i]);
                }
                CP_COMMIT();
                CP_WAIT(1);
            } else {
                CP_WAIT(0);
            }
            __syncthreads();
        }
    }

    #pragma unroll
    for (int mi = 0; mi < 2; mi++) {
        const int r0 = m0 + wm * 32 + mi * 16 + gid;
        #pragma unroll
        for (int nt = 0; nt < 8; nt++) {
            const int n = n0 + wn * 64 + nt * 8 + 2 * tig;
            const float bx = bias[n], by = bias[n + 1];
            if (mode == 0) {
                float2 lo = { __uint_as_float(f2tf((c[0+mi*0][nt][0] + bx) * qs)), 0.f };
                // (written explicitly below to keep mi indexing clear)
                lo.x = __uint_as_float(f2tf((c[mi][nt][0] + bx) * qs));
                lo.y = __uint_as_float(f2tf((c[mi][nt][1] + by) * qs));
                float2 hi;
                hi.x = __uint_as_float(f2tf((c[mi][nt][2] + bx) * qs));
                hi.y = __uint_as_float(f2tf((c[mi][nt][3] + by) * qs));
                const int h = n >> 6, d = n & 63;
                const int b0i = r0 >> 10, s0 = r0 & 1023;
                const int b1i = (r0 + 8) >> 10, s1 = (r0 + 8) & 1023;
                *(float2*)(D + (((size_t)b0i * NH + h) * NS + s0) * ND + d) = lo;
                *(float2*)(D + (((size_t)b1i * NH + h) * NS + s1) * ND + d) = hi;
            } else {
                float2 lo = { c[mi][nt][0] + bx, c[mi][nt][1] + by };
                float2 hi = { c[mi][nt][2] + bx, c[mi][nt][3] + by };
                *(float2*)(D + (size_t)r0 * NE + n) = lo;
                *(float2*)(D + (size_t)(r0 + 8) * NE + n) = hi;
            }
        }
    }
}

// ---------------------------------------------------------------------------
// Flash attention v3: inputs pre-rounded (Q pre-scaled) -> zero cvt on
// K/V/Q paths; only P stores convert. Structure as R4/R5.
// ---------------------------------------------------------------------------
#define QPS 68
#define KSR 68
#define VSR 72
#define OFF_K  (128*QPS)
#define OFF_V  (OFF_K + 2*64*KSR)
#define FLASH_SMEM ((OFF_V + 64*VSR) * 4)   // 88064 B

__global__ __launch_bounds__(128) void flash_kernel()
{
    extern __shared__ float fsm[];
    float* QP = fsm;
    float* Kb = fsm + OFF_K;
    float* Vb = fsm + OFF_V;
    uint32_t* QPu = (uint32_t*)QP;
    uint32_t* Ku  = (uint32_t*)Kb;
    uint32_t* Vu  = (uint32_t*)Vb;
    const uint32_t qp_b = smem_u32(QP);
    const uint32_t k_b  = smem_u32(Kb);
    const uint32_t v_b  = smem_u32(Vb);

    const int qt = blockIdx.x, bh = blockIdx.y;
    const float* Qg = g_q + (size_t)bh * NS * ND + qt * 128 * ND;
    const float* Kg = g_k + (size_t)bh * NS * ND;
    const float* Vg = g_v + (size_t)bh * NS * ND;

    const int tid = threadIdx.x, w = tid >> 5, lane = tid & 31;
    const int gid = lane >> 2, tig = lane & 3;

    #pragma unroll
    for (int i = 0; i < 16; i++) {
        int idx = tid + i * 128, r = idx >> 4, c4 = idx & 15;
        cp16(qp_b + (r * QPS + c4 * 4) * 4, Qg + r * 64 + c4 * 4);
    }
    #pragma unroll
    for (int i = 0; i < 8; i++) {
        int idx = tid + i * 128, r = idx >> 4, c4 = idx & 15;
        cp16(k_b + (r * KSR + c4 * 4) * 4, Kg + r * 64 + c4 * 4);
    }
    CP_COMMIT();
    CP_WAIT(0);
    __syncthreads();

    // hoist Q fragments: raw bits (pre-rounded, pre-scaled)
    uint32_t qf[2][8][4];
    #pragma unroll
    for (int h = 0; h < 2; h++) {
        const int r = w * 32 + h * 16 + gid;
        #pragma unroll
        for (int kk = 0; kk < 8; kk++) {
            qf[h][kk][0] = QPu[(r    ) * QPS + kk * 8 + tig    ];
            qf[h][kk][1] = QPu[(r + 8) * QPS + kk * 8 + tig    ];
            qf[h][kk][2] = QPu[(r    ) * QPS + kk * 8 + tig + 4];
            qf[h][kk][3] = QPu[(r + 8) * QPS + kk * 8 + tig + 4];
        }
    }
    __syncthreads();   // QP becomes P

    #pragma unroll
    for (int i = 0; i < 8; i++) {
        int idx = tid + i * 128, r = idx >> 4, c4 = idx & 15;
        cp16(v_b + (r * VSR + c4 * 4) * 4, Vg + r * 64 + c4 * 4);
    }
    CP_COMMIT();
    #pragma unroll
    for (int i = 0; i < 8; i++) {
        int idx = tid + i * 128, r = idx >> 4, c4 = idx & 15;
        cp16(k_b + (64 * KSR + r * KSR + c4 * 4) * 4, Kg + (64 + r) * 64 + c4 * 4);
    }
    CP_COMMIT();

    float o[2][8][4] = {};
    float mrow[2][2], lrow[2][2];
    #pragma unroll
    for (int h = 0; h < 2; h++) { mrow[h][0] = mrow[h][1] = -1e30f; lrow[h][0] = lrow[h][1] = 0.f; }

    #pragma unroll 1
    for (int kt = 0; kt < 16; kt++) {
        const uint32_t* Kc = Ku + (kt & 1) * 64 * KSR;

        float s[2][8][4] = {};
        #pragma unroll
        for (int kk = 0; kk < 8; kk++) {
            #pragma unroll
            for (int nt = 0; nt < 8; nt++) {
                uint32_t b[2];
                b[0] = Kc[(nt * 8 + gid) * KSR + kk * 8 + tig    ];
                b[1] = Kc[(nt * 8 + gid) * KSR + kk * 8 + tig + 4];
                mma_tf32(s[0][nt], qf[0][kk], b);
                mma_tf32(s[1][nt], qf[1][kk], b);
            }
        }

        #pragma unroll
        for (int h = 0; h < 2; h++) {
            const int r = w * 32 + h * 16 + gid;
            float mx0 = -1e30f, mx1 = -1e30f;
            #pragma unroll
            for (int nt = 0; nt < 8; nt++) {
                mx0 = fmaxf(mx0, fmaxf(s[h][nt][0], s[h][nt][1]));
                mx1 = fmaxf(mx1, fmaxf(s[h][nt][2], s[h][nt][3]));
            }
            #pragma unroll
            for (int off = 1; off < 4; off <<= 1) {
                mx0 = fmaxf(mx0, __shfl_xor_sync(0xffffffffu, mx0, off));
                mx1 = fmaxf(mx1, __shfl_xor_sync(0xffffffffu, mx1, off));
            }
            const float mn0 = fmaxf(mrow[h][0], mx0), mn1 = fmaxf(mrow[h][1], mx1);
            const float al0 = __expf(mrow[h][0] - mn0), al1 = __expf(mrow[h][1] - mn1);
            float rs0 = 0.f, rs1 = 0.f;
            #pragma unroll
            for (int nt = 0; nt < 8; nt++) {
                float p0 = __expf(s[h][nt][0] - mn0);
                float p1 = __expf(s[h][nt][1] - mn0);
                float p2 = __expf(s[h][nt][2] - mn1);
                float p3 = __expf(s[h][nt][3] - mn1);
                rs0 += p0 + p1;  rs1 += p2 + p3;
                const int col = nt * 8 + 2 * tig;
                uint2 w0 = { f2tf(p0), f2tf(p1) };
                uint2 w1 = { f2tf(p2), f2tf(p3) };
                *(uint2*)(&QPu[(r    ) * QPS + col]) = w0;
                *(uint2*)(&QPu[(r + 8) * QPS + col]) = w1;
            }
            #pragma unroll
            for (int off = 1; off < 4; off <<= 1) {
                rs0 += __shfl_xor_sync(0xffffffffu, rs0, off);
                rs1 += __shfl_xor_sync(0xffffffffu, rs1, off);
            }
            lrow[h][0] = lrow[h][0] * al0 + rs0;  mrow[h][0] = mn0;
            lrow[h][1] = lrow[h][1] * al1 + rs1;  mrow[h][1] = mn1;
            #pragma unroll
            for (int nt = 0; nt < 8; nt++) {
                o[h][nt][0] *= al0;  o[h][nt][1] *= al0;
                o[h][nt][2] *= al1;  o[h][nt][3] *= al1;
            }
        }

        if (kt < 15) { CP_WAIT(1); } else { CP_WAIT(0); }
        __syncthreads();

        #pragma unroll
        for (int kk = 0; kk < 8; kk++) {
            uint32_t vb[8][2];
            #pragma unroll
            for (int nt = 0; nt < 8; nt++) {
                vb[nt][0] = Vu[(kk * 8 + tig    ) * VSR + nt * 8 + gid];
                vb[nt][1] = Vu[(kk * 8 + tig + 4) * VSR + nt * 8 + gid];
            }
            #pragma unroll
            for (int h = 0; h < 2; h++) {
                const int r = w * 32 + h * 16 + gid;
                uint32_t a[4];
                a[0] = QPu[(r    ) * QPS + kk * 8 + tig    ];
                a[1] = QPu[(r + 8) * QPS + kk * 8 + tig    ];
                a[2] = QPu[(r    ) * QPS + kk * 8 + tig + 4];
                a[3] = QPu[(r + 8) * QPS + kk * 8 + tig + 4];
                #pragma unroll
                for (int nt = 0; nt < 8; nt++)
                    mma_tf32(o[h][nt], a, vb[nt]);
            }
        }

        if (kt < 15) {
            __syncthreads();
            #pragma unroll
            for (int i = 0; i < 8; i++) {
                int idx = tid + i * 128, r = idx >> 4, c4 = idx & 15;
                cp16(v_b + (r * VSR + c4 * 4) * 4,
                     Vg + (size_t)((kt + 1) * 64 + r) * 64 + c4 * 4);
            }
            CP_COMMIT();
            if (kt < 14) {
                #pragma unroll
                for (int i = 0; i < 8; i++) {
                    int idx = tid + i * 128, r = idx >> 4, c4 = idx & 15;
                    cp16(k_b + ((kt & 1) * 64 * KSR + r * KSR + c4 * 4) * 4,
                         Kg + (size_t)((kt + 2) * 64 + r) * 64 + c4 * 4);
                }
                CP_COMMIT();
                CP_WAIT(2);
            } else {
                CP_WAIT(1);
            }
            __syncthreads();
        }
    }

    // write O (normalized, tf32-rounded) into concat layout [B,S,E]
    const int bb = bh / NH, hh = bh % NH;
    #pragma unroll
    for (int h = 0; h < 2; h++) {
        const float inv0 = 1.0f / lrow[h][0], inv1 = 1.0f / lrow[h][1];
        const int r0 = qt * 128 + w * 32 + h * 16 + gid;
        const int r1 = r0 + 8;
        #pragma unroll
        for (int nt = 0; nt < 8; nt++) {
            const int col = hh * ND + nt * 8 + 2 * tig;
            float2 w0 = { __uint_as_float(f2tf(o[h][nt][0] * inv0)),
                          __uint_as_float(f2tf(o[h][nt][1] * inv0)) };
            float2 w1 = { __uint_as_float(f2tf(o[h][nt][2] * inv1)),
                          __uint_as_float(f2tf(o[h][nt][3] * inv1)) };
            *(float2*)(g_attn + ((size_t)bb * NS + r0) * NE + col) = w0;
            *(float2*)(g_attn + ((size_t)bb * NS + r1) * NE + col) = w1;
        }
    }
}

// ---------------------------------------------------------------------------
extern "C" void kernel_launch(void* const* d_in, const int* in_sizes, int n_in,
                              void* d_out, int out_size)
{
    const float* X  = (const float*)d_in[0];
    const float* Wq = (const float*)d_in[1];
    const float* bq = (const float*)d_in[2];
    const float* Wk = (const float*)d_in[3];
    const float* bk = (const float*)d_in[4];
    const float* Wv = (const float*)d_in[5];
    const float* bv = (const float*)d_in[6];
    const float* Wo = (const float*)d_in[7];
    const float* bo = (const float*)d_in[8];
    float* out = (float*)d_out;

    cudaFuncSetAttribute(gemm_kernel,
                         cudaFuncAttributeMaxDynamicSharedMemorySize, GEMM_SMEM);
    cudaFuncSetAttribute(flash_kernel,
                         cudaFuncAttributeMaxDynamicSharedMemorySize, FLASH_SMEM);

    const int nround = (NX4 + 4 * NW4 + 255) / 256;   // 8448 blocks
    round_kernel<<<nround, 256>>>(X, Wq, Wk, Wv, Wo);

    gemm_kernel<<<dim3(NT/128, NE/128, 3), 256, GEMM_SMEM>>>(
        bq, bk, bv, nullptr, 0);

    flash_kernel<<<dim3(NS/128, NB*NH), 128, FLASH_SMEM>>>();

    gemm_kernel<<<dim3(NT/128, NE/128, 1), 256, GEMM_SMEM>>>(
        bo, bo, bo, out, 1);
}

// round 8
// speedup vs baseline: 1.2742x; 1.0516x over previous
#include <cuda_runtime.h>
#include <cstdint>

#define NB 8
#define NS 1024
#define NE 768
#define NH 12
#define ND 64
#define NT (NB*NS)   // 8192 tokens

// Scratch (device globals: allocation-free rule)
__device__ float g_q[NB*NH*NS*ND];     // [B,H,S,D], tf32-rounded, Q pre-scaled
__device__ float g_k[NB*NH*NS*ND];
__device__ float g_v[NB*NH*NS*ND];
__device__ float g_attn[NT*NE];        // [B,S,E], tf32-rounded
__device__ float g_xr[NT*NE];          // tf32-rounded X
__device__ float g_wr[4*NE*NE];        // tf32-rounded Wq,Wk,Wv,Wo

// ---------------------------------------------------------------------------
__device__ __forceinline__ uint32_t f2tf(float f) {
    uint32_t r;
    asm("cvt.rna.tf32.f32 %0, %1;" : "=r"(r) : "f"(f));
    return r;
}
__device__ __forceinline__ void mma_tf32(float* d, const uint32_t* a, const uint32_t* b) {
    asm volatile(
        "mma.sync.aligned.m16n8k8.row.col.f32.tf32.tf32.f32 "
        "{%0,%1,%2,%3}, {%4,%5,%6,%7}, {%8,%9}, {%0,%1,%2,%3};"
        : "+f"(d[0]), "+f"(d[1]), "+f"(d[2]), "+f"(d[3])
        : "r"(a[0]), "r"(a[1]), "r"(a[2]), "r"(a[3]), "r"(b[0]), "r"(b[1]));
}
__device__ __forceinline__ void ldsm4(uint32_t* r, uint32_t addr) {
    asm volatile("ldmatrix.sync.aligned.m8n8.x4.shared.b16 {%0,%1,%2,%3}, [%4];"
        : "=r"(r[0]), "=r"(r[1]), "=r"(r[2]), "=r"(r[3]) : "r"(addr));
}
__device__ __forceinline__ uint32_t smem_u32(const void* p) {
    uint32_t a;
    asm("{ .reg .u64 t; cvta.to.shared.u64 t, %1; cvt.u32.u64 %0, t; }"
        : "=r"(a) : "l"(p));
    return a;
}
__device__ __forceinline__ void cp16(uint32_t dst, const void* src) {
    asm volatile("cp.async.cg.shared.global [%0], [%1], 16;"
                 :: "r"(dst), "l"(src) : "memory");
}
#define CP_COMMIT() asm volatile("cp.async.commit_group;" ::: "memory")
#define CP_WAIT(n)  asm volatile("cp.async.wait_group %0;" :: "n"(n) : "memory")

// ---------------------------------------------------------------------------
// Kernel 0: round X and all weights to tf32 (rna) once.
// ---------------------------------------------------------------------------
#define NX4 (NT*NE/4)      // 1572864
#define NW4 (NE*NE/4)      // 147456

__global__ __launch_bounds__(256) void round_kernel(
    const float* __restrict__ X,
    const float* __restrict__ Wq, const float* __restrict__ Wk,
    const float* __restrict__ Wv, const float* __restrict__ Wo)
{
    int idx = blockIdx.x * 256 + threadIdx.x;
    const float4* src4;
    float4* dst4;
    if (idx < NX4) {
        src4 = (const float4*)X + idx;
        dst4 = (float4*)g_xr + idx;
    } else {
        int j = idx - NX4;
        int w = j / NW4, o = j - w * NW4;
        const float* s = (w == 0) ? Wq : (w == 1) ? Wk : (w == 2) ? Wv : Wo;
        src4 = (const float4*)s + o;
        dst4 = (float4*)(g_wr + (size_t)w * NE * NE) + o;
    }
    float4 v = *src4;
    float4 r;
    r.x = __uint_as_float(f2tf(v.x));
    r.y = __uint_as_float(f2tf(v.y));
    r.z = __uint_as_float(f2tf(v.z));
    r.w = __uint_as_float(f2tf(v.w));
    *dst4 = r;
}

// ---------------------------------------------------------------------------
// GEMM v5: BM=128 BN=128 BK=32, 3-stage cp.async, ONE barrier per k-block,
// loads issued before compute, ldmatrix A-frags. 2 CTAs/SM.
// mode 0: z picks Wq/Wk/Wv -> g_q/g_k/g_v (tf32-rounded, Q scaled 1/8).
// mode 1: Wo, A = g_attn -> Dext (plain f32 + bias, final output).
// ---------------------------------------------------------------------------
#define GASTR 36
#define GBSTR 136
#define AST (128*GASTR)     // 4608 words per A stage
#define BST (32*GBSTR)      // 4352 words per B stage
#define GEMM_SMEM ((3*AST + 3*BST) * 4)   // 107520 B

__global__ __launch_bounds__(256, 2) void gemm_kernel(
    const float* __restrict__ b0_, const float* __restrict__ b1_,
    const float* __restrict__ b2_,
    float* __restrict__ Dext, int mode)
{
    extern __shared__ uint32_t gsm[];
    uint32_t* As = gsm;                // [3][AST]
    uint32_t* Bs = gsm + 3 * AST;      // [3][BST]
    const uint32_t ua = smem_u32(As);
    const uint32_t ub = smem_u32(Bs);

    const int z = blockIdx.z;
    const float* A = (mode == 0) ? g_xr : g_attn;
    const float* W = g_wr + (size_t)((mode == 0) ? z : 3) * NE * NE;
    const float* bias = (mode == 0) ? (z == 0 ? b0_ : z == 1 ? b1_ : b2_) : b0_;
    float* D = (mode == 0) ? (z == 0 ? g_q : z == 1 ? g_k : g_v) : Dext;
    const float qs = (mode == 0 && z == 0) ? 0.125f : 1.0f;

    const int tid = threadIdx.x, wid = tid >> 5, lane = tid & 31;
    const int gid = lane >> 2, tig = lane & 3;
    const int wm = wid >> 1, wn = wid & 1;
    const int m0 = blockIdx.x * 128, n0 = blockIdx.y * 128;

    // staging: A 128x32 (4 cp16/thread), B 32x128 (4 cp16/thread)
    int ar[4], ac[4], brr[4], bcc[4];
    #pragma unroll
    for (int i = 0; i < 4; i++) {
        int idx = tid + i * 256;
        ar[i] = idx >> 3;  ac[i] = (idx & 7) * 4;
        brr[i] = idx >> 5; bcc[i] = (idx & 31) * 4;
    }

    // ldmatrix per-lane geometry for A-frags
    const int lrow  = (lane & 7) + ((lane >> 3) & 1) * 8;   // 0..15
    const int lcolh = (lane >> 4) * 4;                       // 0 or 4
    uint32_t a_base[2];
    #pragma unroll
    for (int mi = 0; mi < 2; mi++)
        a_base[mi] = (uint32_t)((wm * 32 + mi * 16 + lrow) * GASTR + lcolh);

    // prologue: stages 0, 1
    #pragma unroll
    for (int s = 0; s < 2; s++) {
        #pragma unroll
        for (int i = 0; i < 4; i++) {
            cp16(ua + (s * AST + ar[i] * GASTR + ac[i]) * 4,
                 A + (size_t)(m0 + ar[i]) * NE + s * 32 + ac[i]);
            cp16(ub + (s * BST + brr[i] * GBSTR + bcc[i]) * 4,
                 W + (size_t)(s * 32 + brr[i]) * NE + n0 + bcc[i]);
        }
        CP_COMMIT();
    }
    CP_WAIT(1);
    __syncthreads();

    float c[2][8][4] = {};

    int cur = 0;
    #pragma unroll 1
    for (int kb = 0; kb < 24; kb++) {
        // issue loads for kb+2 into slot (cur+2)%3 (freed by last barrier)
        if (kb < 22) {
            const int sl = (cur + 2) % 3;
            const int kn = (kb + 2) * 32;
            #pragma unroll
            for (int i = 0; i < 4; i++) {
                cp16(ua + (sl * AST + ar[i] * GASTR + ac[i]) * 4,
                     A + (size_t)(m0 + ar[i]) * NE + kn + ac[i]);
                cp16(ub + (sl * BST + brr[i] * GBSTR + bcc[i]) * 4,
                     W + (size_t)(kn + brr[i]) * NE + n0 + bcc[i]);
            }
            CP_COMMIT();
        }

        const uint32_t a_st = ua + (cur * AST) * 4;
        const uint32_t* Bb = Bs + cur * BST;
        #pragma unroll
        for (int kk = 0; kk < 4; kk++) {
            uint32_t a[2][4];
            ldsm4(a[0], a_st + (a_base[0] + kk * 8) * 4);
            ldsm4(a[1], a_st + (a_base[1] + kk * 8) * 4);
            #pragma unroll
            for (int nt = 0; nt < 8; nt++) {
                uint32_t b[2];
                const int nc = wn * 64 + nt * 8 + gid;
                b[0] = Bb[(kk * 8 + tig    ) * GBSTR + nc];
                b[1] = Bb[(kk * 8 + tig + 4) * GBSTR + nc];
                mma_tf32(c[0][nt], a[0], b);
                mma_tf32(c[1][nt], a[1], b);
            }
        }

        if (kb < 23) {
            if (kb < 22) { CP_WAIT(1); } else { CP_WAIT(0); }
            __syncthreads();
        }
        cur = (cur == 2) ? 0 : cur + 1;
    }

    #pragma unroll
    for (int mi = 0; mi < 2; mi++) {
        const int r0 = m0 + wm * 32 + mi * 16 + gid;
        #pragma unroll
        for (int nt = 0; nt < 8; nt++) {
            const int n = n0 + wn * 64 + nt * 8 + 2 * tig;
            const float bx = bias[n], by = bias[n + 1];
            if (mode == 0) {
                float2 lo, hi;
                lo.x = __uint_as_float(f2tf((c[mi][nt][0] + bx) * qs));
                lo.y = __uint_as_float(f2tf((c[mi][nt][1] + by) * qs));
                hi.x = __uint_as_float(f2tf((c[mi][nt][2] + bx) * qs));
                hi.y = __uint_as_float(f2tf((c[mi][nt][3] + by) * qs));
                const int h = n >> 6, d = n & 63;
                const int b0i = r0 >> 10, s0 = r0 & 1023;
                const int b1i = (r0 + 8) >> 10, s1 = (r0 + 8) & 1023;
                *(float2*)(D + (((size_t)b0i * NH + h) * NS + s0) * ND + d) = lo;
                *(float2*)(D + (((size_t)b1i * NH + h) * NS + s1) * ND + d) = hi;
            } else {
                float2 lo = { c[mi][nt][0] + bx, c[mi][nt][1] + by };
                float2 hi = { c[mi][nt][2] + bx, c[mi][nt][3] + by };
                *(float2*)(D + (size_t)r0 * NE + n) = lo;
                *(float2*)(D + (size_t)(r0 + 8) * NE + n) = hi;
            }
        }
    }
}

// ---------------------------------------------------------------------------
// Flash attention v4: P entirely in registers (V row-permutation trick),
// ldmatrix K b-frags, K and V double-buffered, ONE barrier per kt.
// grid=(8, 96), 128 threads (4 warps), Q tile 128 rows (32/warp).
// ---------------------------------------------------------------------------
#define QPS 68
#define KSR 68
#define VSR 68
#define KOFF 8704                      // words: Q = 128*68
#define VOFF (KOFF + 2*64*KSR)         // 17408
#define KSTG (64*KSR)                  // 4352 words per K/V stage
#define FLASH_SMEM ((VOFF + 2*64*VSR) * 4)   // 104448 B

__global__ __launch_bounds__(128) void flash_kernel()
{
    extern __shared__ float fsm[];
    float* QP = fsm;
    uint32_t* QPu = (uint32_t*)QP;
    const uint32_t sb = smem_u32(fsm);

    const int qt = blockIdx.x, bh = blockIdx.y;
    const float* Qg = g_q + (size_t)bh * NS * ND + qt * 128 * ND;
    const float* Kg = g_k + (size_t)bh * NS * ND;
    const float* Vg = g_v + (size_t)bh * NS * ND;

    const int tid = threadIdx.x, w = tid >> 5, lane = tid & 31;
    const int gid = lane >> 2, tig = lane & 3;

    // ldmatrix per-lane geometry for K b-frags
    const int ktok = (lane & 7) + ((lane >> 4) << 3);   // 0..15
    const int kcol = ((lane >> 3) & 1) * 4;             // 0 or 4
    const uint32_t kfrag = (uint32_t)(ktok * KSR + kcol);

    // stage Q + K0 + V0
    #pragma unroll
    for (int i = 0; i < 16; i++) {
        int idx = tid + i * 128, r = idx >> 4, c4 = idx & 15;
        cp16(sb + (r * QPS + c4 * 4) * 4, Qg + r * 64 + c4 * 4);
    }
    #pragma unroll
    for (int i = 0; i < 8; i++) {
        int idx = tid + i * 128, r = idx >> 4, c4 = idx & 15;
        cp16(sb + (KOFF + r * KSR + c4 * 4) * 4, Kg + r * 64 + c4 * 4);
        cp16(sb + (VOFF + r * VSR + c4 * 4) * 4, Vg + r * 64 + c4 * 4);
    }
    CP_COMMIT();
    CP_WAIT(0);
    __syncthreads();

    // hoist Q fragments (pre-rounded, pre-scaled) — raw bits
    uint32_t qf[2][8][4];
    #pragma unroll
    for (int h = 0; h < 2; h++) {
        const int r = w * 32 + h * 16 + gid;
        #pragma unroll
        for (int kk = 0; kk < 8; kk++) {
            qf[h][kk][0] = QPu[(r    ) * QPS + kk * 8 + tig    ];
            qf[h][kk][1] = QPu[(r + 8) * QPS + kk * 8 + tig    ];
            qf[h][kk][2] = QPu[(r    ) * QPS + kk * 8 + tig + 4];
            qf[h][kk][3] = QPu[(r + 8) * QPS + kk * 8 + tig + 4];
        }
    }

    float o[2][8][4] = {};
    float mrow[2][2], lrow[2][2];
    #pragma unroll
    for (int h = 0; h < 2; h++) { mrow[h][0] = mrow[h][1] = -1e30f; lrow[h][0] = lrow[h][1] = 0.f; }

    #pragma unroll 1
    for (int kt = 0; kt < 16; kt++) {
        // prefetch K[kt+1], V[kt+1] into the buffers freed by the last barrier
        if (kt < 15) {
            const int sl = (kt + 1) & 1;
            const float* kg = Kg + (size_t)(kt + 1) * 64 * 64;
            const float* vg = Vg + (size_t)(kt + 1) * 64 * 64;
            #pragma unroll
            for (int i = 0; i < 8; i++) {
                int idx = tid + i * 128, r = idx >> 4, c4 = idx & 15;
                cp16(sb + (KOFF + sl * KSTG + r * KSR + c4 * 4) * 4, kg + r * 64 + c4 * 4);
                cp16(sb + (VOFF + sl * KSTG + r * VSR + c4 * 4) * 4, vg + r * 64 + c4 * 4);
            }
            CP_COMMIT();
        }

        // S = Q @ K^T via ldmatrix b-frags
        const uint32_t kbase = sb + (KOFF + (kt & 1) * KSTG) * 4;
        float s[2][8][4] = {};
        #pragma unroll
        for (int kk = 0; kk < 8; kk++) {
            #pragma unroll
            for (int ntp = 0; ntp < 4; ntp++) {
                uint32_t kb4[4];
                ldsm4(kb4, kbase + (ntp * 16 * KSR + kk * 8 + kfrag) * 4);
                mma_tf32(s[0][2*ntp    ], qf[0][kk], kb4);
                mma_tf32(s[0][2*ntp + 1], qf[0][kk], kb4 + 2);
                mma_tf32(s[1][2*ntp    ], qf[1][kk], kb4);
                mma_tf32(s[1][2*ntp + 1], qf[1][kk], kb4 + 2);
            }
        }

        // online softmax; P stays in registers (overwrite s with tf32 bits)
        #pragma unroll
        for (int h = 0; h < 2; h++) {
            float mx0 = -1e30f, mx1 = -1e30f;
            #pragma unroll
            for (int nt = 0; nt < 8; nt++) {
                mx0 = fmaxf(mx0, fmaxf(s[h][nt][0], s[h][nt][1]));
                mx1 = fmaxf(mx1, fmaxf(s[h][nt][2], s[h][nt][3]));
            }
            #pragma unroll
            for (int off = 1; off < 4; off <<= 1) {
                mx0 = fmaxf(mx0, __shfl_xor_sync(0xffffffffu, mx0, off));
                mx1 = fmaxf(mx1, __shfl_xor_sync(0xffffffffu, mx1, off));
            }
            const float mn0 = fmaxf(mrow[h][0], mx0), mn1 = fmaxf(mrow[h][1], mx1);
            const float al0 = __expf(mrow[h][0] - mn0), al1 = __expf(mrow[h][1] - mn1);
            float rs0 = 0.f, rs1 = 0.f;
            #pragma unroll
            for (int nt = 0; nt < 8; nt++) {
                float p0 = __expf(s[h][nt][0] - mn0);
                float p1 = __expf(s[h][nt][1] - mn0);
                float p2 = __expf(s[h][nt][2] - mn1);
                float p3 = __expf(s[h][nt][3] - mn1);
                rs0 += p0 + p1;  rs1 += p2 + p3;
                s[h][nt][0] = __uint_as_float(f2tf(p0));
                s[h][nt][1] = __uint_as_float(f2tf(p1));
                s[h][nt][2] = __uint_as_float(f2tf(p2));
                s[h][nt][3] = __uint_as_float(f2tf(p3));
            }
            #pragma unroll
            for (int off = 1; off < 4; off <<= 1) {
                rs0 += __shfl_xor_sync(0xffffffffu, rs0, off);
                rs1 += __shfl_xor_sync(0xffffffffu, rs1, off);
            }
            lrow[h][0] = lrow[h][0] * al0 + rs0;  mrow[h][0] = mn0;
            lrow[h][1] = lrow[h][1] * al1 + rs1;  mrow[h][1] = mn1;
            #pragma unroll
            for (int nt = 0; nt < 8; nt++) {
                o[h][nt][0] *= al0;  o[h][nt][1] *= al0;
                o[h][nt][2] *= al1;  o[h][nt][3] *= al1;
            }
        }

        // O += P @ V. V rows read permuted (2*tig, 2*tig+1) so the S C-frag
        // registers ARE the A-frag (order {c0,c2,c1,c3}). Same permutation on
        // both sides of the k-reduction -> exact.
        const uint32_t* Vu = (uint32_t*)fsm + VOFF + (kt & 1) * KSTG;
        #pragma unroll
        for (int kk = 0; kk < 8; kk++) {
            uint32_t vb[8][2];
            #pragma unroll
            for (int nt = 0; nt < 8; nt++) {
                vb[nt][0] = Vu[(kk * 8 + 2 * tig    ) * VSR + nt * 8 + gid];
                vb[nt][1] = Vu[(kk * 8 + 2 * tig + 1) * VSR + nt * 8 + gid];
            }
            #pragma unroll
            for (int h = 0; h < 2; h++) {
                uint32_t a[4];
                a[0] = __float_as_uint(s[h][kk][0]);
                a[1] = __float_as_uint(s[h][kk][2]);
                a[2] = __float_as_uint(s[h][kk][1]);
                a[3] = __float_as_uint(s[h][kk][3]);
                #pragma unroll
                for (int nt = 0; nt < 8; nt++)
                    mma_tf32(o[h][nt], a, vb[nt]);
            }
        }

        if (kt < 15) {
            CP_WAIT(0);
            __syncthreads();
        }
    }

    // write O (normalized, tf32-rounded) into concat layout [B,S,E]
    const int bb = bh / NH, hh = bh % NH;
    #pragma unroll
    for (int h = 0; h < 2; h++) {
        const float inv0 = 1.0f / lrow[h][0], inv1 = 1.0f / lrow[h][1];
        const int r0 = qt * 128 + w * 32 + h * 16 + gid;
        const int r1 = r0 + 8;
        #pragma unroll
        for (int nt = 0; nt < 8; nt++) {
            const int col = hh * ND + nt * 8 + 2 * tig;
            float2 w0 = { __uint_as_float(f2tf(o[h][nt][0] * inv0)),
                          __uint_as_float(f2tf(o[h][nt][1] * inv0)) };
            float2 w1 = { __uint_as_float(f2tf(o[h][nt][2] * inv1)),
                          __uint_as_float(f2tf(o[h][nt][3] * inv1)) };
            *(float2*)(g_attn + ((size_t)bb * NS + r0) * NE + col) = w0;
            *(float2*)(g_attn + ((size_t)bb * NS + r1) * NE + col) = w1;
        }
    }
}

// ---------------------------------------------------------------------------
extern "C" void kernel_launch(void* const* d_in, const int* in_sizes, int n_in,
                              void* d_out, int out_size)
{
    const float* X  = (const float*)d_in[0];
    const float* Wq = (const float*)d_in[1];
    const float* bq = (const float*)d_in[2];
    const float* Wk = (const float*)d_in[3];
    const float* bk = (const float*)d_in[4];
    const float* Wv = (const float*)d_in[5];
    const float* bv = (const float*)d_in[6];
    const float* Wo = (const float*)d_in[7];
    const float* bo = (const float*)d_in[8];
    float* out = (float*)d_out;

    cudaFuncSetAttribute(gemm_kernel,
                         cudaFuncAttributeMaxDynamicSharedMemorySize, GEMM_SMEM);
    cudaFuncSetAttribute(flash_kernel,
                         cudaFuncAttributeMaxDynamicSharedMemorySize, FLASH_SMEM);

    const int nround = (NX4 + 4 * NW4 + 255) / 256;   // 8448 blocks
    round_kernel<<<nround, 256>>>(X, Wq, Wk, Wv, Wo);

    gemm_kernel<<<dim3(NT/128, NE/128, 3), 256, GEMM_SMEM>>>(
        bq, bk, bv, nullptr, 0);

    flash_kernel<<<dim3(NS/128, NB*NH), 128, FLASH_SMEM>>>();

    gemm_kernel<<<dim3(NT/128, NE/128, 1), 256, GEMM_SMEM>>>(
        bo, bo, bo, out, 1);
}

// round 9
// speedup vs baseline: 1.2849x; 1.0084x over previous
#include <cuda_runtime.h>
#include <cstdint>

#define NB 8
#define NS 1024
#define NE 768
#define NH 12
#define ND 64
#define NT (NB*NS)   // 8192 tokens

// Scratch (device globals: allocation-free rule)
__device__ float g_q[NB*NH*NS*ND];     // [B,H,S,D], tf32-rounded, Q scaled by log2e/8
__device__ float g_k[NB*NH*NS*ND];
__device__ float g_v[NB*NH*NS*ND];
__device__ float g_attn[NT*NE];        // [B,S,E], tf32-rounded
__device__ float g_xr[NT*NE];          // tf32-rounded X
__device__ float g_wr[4*NE*NE];        // tf32-rounded Wq,Wk,Wv,Wo

// ---------------------------------------------------------------------------
__device__ __forceinline__ uint32_t f2tf(float f) {
    uint32_t r;
    asm("cvt.rna.tf32.f32 %0, %1;" : "=r"(r) : "f"(f));
    return r;
}
__device__ __forceinline__ float ex2f(float x) {
    float r;
    asm("ex2.approx.ftz.f32 %0, %1;" : "=f"(r) : "f"(x));
    return r;
}
__device__ __forceinline__ void mma_tf32(float* d, const uint32_t* a, const uint32_t* b) {
    asm volatile(
        "mma.sync.aligned.m16n8k8.row.col.f32.tf32.tf32.f32 "
        "{%0,%1,%2,%3}, {%4,%5,%6,%7}, {%8,%9}, {%0,%1,%2,%3};"
        : "+f"(d[0]), "+f"(d[1]), "+f"(d[2]), "+f"(d[3])
        : "r"(a[0]), "r"(a[1]), "r"(a[2]), "r"(a[3]), "r"(b[0]), "r"(b[1]));
}
__device__ __forceinline__ void ldsm4(uint32_t* r, uint32_t addr) {
    asm volatile("ldmatrix.sync.aligned.m8n8.x4.shared.b16 {%0,%1,%2,%3}, [%4];"
        : "=r"(r[0]), "=r"(r[1]), "=r"(r[2]), "=r"(r[3]) : "r"(addr));
}
__device__ __forceinline__ uint32_t smem_u32(const void* p) {
    uint32_t a;
    asm("{ .reg .u64 t; cvta.to.shared.u64 t, %1; cvt.u32.u64 %0, t; }"
        : "=r"(a) : "l"(p));
    return a;
}
__device__ __forceinline__ void cp16(uint32_t dst, const void* src) {
    asm volatile("cp.async.cg.shared.global [%0], [%1], 16;"
                 :: "r"(dst), "l"(src) : "memory");
}
#define CP_COMMIT() asm volatile("cp.async.commit_group;" ::: "memory")
#define CP_WAIT(n)  asm volatile("cp.async.wait_group %0;" :: "n"(n) : "memory")

// ---------------------------------------------------------------------------
// Kernel 0: round X and all weights to tf32 (rna) once.
// ---------------------------------------------------------------------------
#define NX4 (NT*NE/4)      // 1572864
#define NW4 (NE*NE/4)      // 147456

__global__ __launch_bounds__(256) void round_kernel(
    const float* __restrict__ X,
    const float* __restrict__ Wq, const float* __restrict__ Wk,
    const float* __restrict__ Wv, const float* __restrict__ Wo)
{
    int idx = blockIdx.x * 256 + threadIdx.x;
    const float4* src4;
    float4* dst4;
    if (idx < NX4) {
        src4 = (const float4*)X + idx;
        dst4 = (float4*)g_xr + idx;
    } else {
        int j = idx - NX4;
        int w = j / NW4, o = j - w * NW4;
        const float* s = (w == 0) ? Wq : (w == 1) ? Wk : (w == 2) ? Wv : Wo;
        src4 = (const float4*)s + o;
        dst4 = (float4*)(g_wr + (size_t)w * NE * NE) + o;
    }
    float4 v = *src4;
    float4 r;
    r.x = __uint_as_float(f2tf(v.x));
    r.y = __uint_as_float(f2tf(v.y));
    r.z = __uint_as_float(f2tf(v.z));
    r.w = __uint_as_float(f2tf(v.w));
    *dst4 = r;
}

// ---------------------------------------------------------------------------
// GEMM v5 (unchanged from R8): BM=128 BN=128 BK=32, 3-stage cp.async,
// one barrier per k-block, ldmatrix A-frags, 2 CTAs/SM.
// mode 0: z picks Wq/Wk/Wv -> g_q/g_k/g_v (tf32-rounded; Q scaled log2e/8).
// mode 1: Wo, A = g_attn -> Dext (plain f32 + bias, final output).
// ---------------------------------------------------------------------------
#define GASTR 36
#define GBSTR 136
#define AST (128*GASTR)
#define BST (32*GBSTR)
#define GEMM_SMEM ((3*AST + 3*BST) * 4)   // 107520 B
#define QSCALE 0.18033688011112042f       // 0.125 * log2(e)

__global__ __launch_bounds__(256, 2) void gemm_kernel(
    const float* __restrict__ b0_, const float* __restrict__ b1_,
    const float* __restrict__ b2_,
    float* __restrict__ Dext, int mode)
{
    extern __shared__ uint32_t gsm[];
    uint32_t* As = gsm;
    uint32_t* Bs = gsm + 3 * AST;
    const uint32_t ua = smem_u32(As);
    const uint32_t ub = smem_u32(Bs);

    const int z = blockIdx.z;
    const float* A = (mode == 0) ? g_xr : g_attn;
    const float* W = g_wr + (size_t)((mode == 0) ? z : 3) * NE * NE;
    const float* bias = (mode == 0) ? (z == 0 ? b0_ : z == 1 ? b1_ : b2_) : b0_;
    float* D = (mode == 0) ? (z == 0 ? g_q : z == 1 ? g_k : g_v) : Dext;
    const float qs = (mode == 0 && z == 0) ? QSCALE : 1.0f;

    const int tid = threadIdx.x, wid = tid >> 5, lane = tid & 31;
    const int gid = lane >> 2, tig = lane & 3;
    const int wm = wid >> 1, wn = wid & 1;
    const int m0 = blockIdx.x * 128, n0 = blockIdx.y * 128;

    int ar[4], ac[4], brr[4], bcc[4];
    #pragma unroll
    for (int i = 0; i < 4; i++) {
        int idx = tid + i * 256;
        ar[i] = idx >> 3;  ac[i] = (idx & 7) * 4;
        brr[i] = idx >> 5; bcc[i] = (idx & 31) * 4;
    }

    const int lrow  = (lane & 7) + ((lane >> 3) & 1) * 8;
    const int lcolh = (lane >> 4) * 4;
    uint32_t a_base[2];
    #pragma unroll
    for (int mi = 0; mi < 2; mi++)
        a_base[mi] = (uint32_t)((wm * 32 + mi * 16 + lrow) * GASTR + lcolh);

    #pragma unroll
    for (int s = 0; s < 2; s++) {
        #pragma unroll
        for (int i = 0; i < 4; i++) {
            cp16(ua + (s * AST + ar[i] * GASTR + ac[i]) * 4,
                 A + (size_t)(m0 + ar[i]) * NE + s * 32 + ac[i]);
            cp16(ub + (s * BST + brr[i] * GBSTR + bcc[i]) * 4,
                 W + (size_t)(s * 32 + brr[i]) * NE + n0 + bcc[i]);
        }
        CP_COMMIT();
    }
    CP_WAIT(1);
    __syncthreads();

    float c[2][8][4] = {};

    int cur = 0;
    #pragma unroll 1
    for (int kb = 0; kb < 24; kb++) {
        if (kb < 22) {
            const int sl = (cur + 2) % 3;
            const int kn = (kb + 2) * 32;
            #pragma unroll
            for (int i = 0; i < 4; i++) {
                cp16(ua + (sl * AST + ar[i] * GASTR + ac[i]) * 4,
                     A + (size_t)(m0 + ar[i]) * NE + kn + ac[i]);
                cp16(ub + (sl * BST + brr[i] * GBSTR + bcc[i]) * 4,
                     W + (size_t)(kn + brr[i]) * NE + n0 + bcc[i]);
            }
            CP_COMMIT();
        }

        const uint32_t a_st = ua + (cur * AST) * 4;
        const uint32_t* Bb = Bs + cur * BST;
        #pragma unroll
        for (int kk = 0; kk < 4; kk++) {
            uint32_t a[2][4];
            ldsm4(a[0], a_st + (a_base[0] + kk * 8) * 4);
            ldsm4(a[1], a_st + (a_base[1] + kk * 8) * 4);
            #pragma unroll
            for (int nt = 0; nt < 8; nt++) {
                uint32_t b[2];
                const int nc = wn * 64 + nt * 8 + gid;
                b[0] = Bb[(kk * 8 + tig    ) * GBSTR + nc];
                b[1] = Bb[(kk * 8 + tig + 4) * GBSTR + nc];
                mma_tf32(c[0][nt], a[0], b);
                mma_tf32(c[1][nt], a[1], b);
            }
        }

        if (kb < 23) {
            if (kb < 22) { CP_WAIT(1); } else { CP_WAIT(0); }
            __syncthreads();
        }
        cur = (cur == 2) ? 0 : cur + 1;
    }

    #pragma unroll
    for (int mi = 0; mi < 2; mi++) {
        const int r0 = m0 + wm * 32 + mi * 16 + gid;
        #pragma unroll
        for (int nt = 0; nt < 8; nt++) {
            const int n = n0 + wn * 64 + nt * 8 + 2 * tig;
            const float bx = bias[n], by = bias[n + 1];
            if (mode == 0) {
                float2 lo, hi;
                lo.x = __uint_as_float(f2tf((c[mi][nt][0] + bx) * qs));
                lo.y = __uint_as_float(f2tf((c[mi][nt][1] + by) * qs));
                hi.x = __uint_as_float(f2tf((c[mi][nt][2] + bx) * qs));
                hi.y = __uint_as_float(f2tf((c[mi][nt][3] + by) * qs));
                const int h = n >> 6, d = n & 63;
                const int b0i = r0 >> 10, s0 = r0 & 1023;
                const int b1i = (r0 + 8) >> 10, s1 = (r0 + 8) & 1023;
                *(float2*)(D + (((size_t)b0i * NH + h) * NS + s0) * ND + d) = lo;
                *(float2*)(D + (((size_t)b1i * NH + h) * NS + s1) * ND + d) = hi;
            } else {
                float2 lo = { c[mi][nt][0] + bx, c[mi][nt][1] + by };
                float2 hi = { c[mi][nt][2] + bx, c[mi][nt][3] + by };
                *(float2*)(D + (size_t)r0 * NE + n) = lo;
                *(float2*)(D + (size_t)(r0 + 8) * NE + n) = hi;
            }
        }
    }
}

// ---------------------------------------------------------------------------
// Flash attention v5: 256 threads / 8 warps, 16 Q-rows per warp.
// P in registers, ldmatrix K b-frags, K/V double-buffered, one barrier/kt,
// ex2-based softmax (Q pre-scaled by log2e/8 in the QKV epilogue).
// grid=(8, 96). smem 104448 B -> 2 CTAs/SM -> 16 warps/SM.
// ---------------------------------------------------------------------------
#define QPS 68
#define KSR 68
#define VSR 68
#define KOFF 8704                      // words: Q = 128*68
#define VOFF (KOFF + 2*64*KSR)
#define KSTG (64*KSR)
#define FLASH_SMEM ((VOFF + 2*64*VSR) * 4)   // 104448 B

__global__ __launch_bounds__(256) void flash_kernel()
{
    extern __shared__ float fsm[];
    uint32_t* QPu = (uint32_t*)fsm;
    const uint32_t sb = smem_u32(fsm);

    const int qt = blockIdx.x, bh = blockIdx.y;
    const float* Qg = g_q + (size_t)bh * NS * ND + qt * 128 * ND;
    const float* Kg = g_k + (size_t)bh * NS * ND;
    const float* Vg = g_v + (size_t)bh * NS * ND;

    const int tid = threadIdx.x, w = tid >> 5, lane = tid & 31;
    const int gid = lane >> 2, tig = lane & 3;

    const int ktok = (lane & 7) + ((lane >> 4) << 3);
    const int kcol = ((lane >> 3) & 1) * 4;
    const uint32_t kfrag = (uint32_t)(ktok * KSR + kcol);

    // stage Q + K0 + V0 (256 threads)
    #pragma unroll
    for (int i = 0; i < 8; i++) {
        int idx = tid + i * 256, r = idx >> 4, c4 = idx & 15;
        cp16(sb + (r * QPS + c4 * 4) * 4, Qg + r * 64 + c4 * 4);
    }
    #pragma unroll
    for (int i = 0; i < 4; i++) {
        int idx = tid + i * 256, r = idx >> 4, c4 = idx & 15;
        cp16(sb + (KOFF + r * KSR + c4 * 4) * 4, Kg + r * 64 + c4 * 4);
        cp16(sb + (VOFF + r * VSR + c4 * 4) * 4, Vg + r * 64 + c4 * 4);
    }
    CP_COMMIT();
    CP_WAIT(0);
    __syncthreads();

    // hoist Q fragments (16 rows per warp) — raw bits
    uint32_t qf[8][4];
    {
        const int r = w * 16 + gid;
        #pragma unroll
        for (int kk = 0; kk < 8; kk++) {
            qf[kk][0] = QPu[(r    ) * QPS + kk * 8 + tig    ];
            qf[kk][1] = QPu[(r + 8) * QPS + kk * 8 + tig    ];
            qf[kk][2] = QPu[(r    ) * QPS + kk * 8 + tig + 4];
            qf[kk][3] = QPu[(r + 8) * QPS + kk * 8 + tig + 4];
        }
    }

    float o[8][4] = {};
    float m0r = -1e30f, m1r = -1e30f, l0 = 0.f, l1 = 0.f;

    #pragma unroll 1
    for (int kt = 0; kt < 16; kt++) {
        // prefetch K[kt+1], V[kt+1]
        if (kt < 15) {
            const int sl = (kt + 1) & 1;
            const float* kg = Kg + (size_t)(kt + 1) * 64 * 64;
            const float* vg = Vg + (size_t)(kt + 1) * 64 * 64;
            #pragma unroll
            for (int i = 0; i < 4; i++) {
                int idx = tid + i * 256, r = idx >> 4, c4 = idx & 15;
                cp16(sb + (KOFF + sl * KSTG + r * KSR + c4 * 4) * 4, kg + r * 64 + c4 * 4);
                cp16(sb + (VOFF + sl * KSTG + r * VSR + c4 * 4) * 4, vg + r * 64 + c4 * 4);
            }
            CP_COMMIT();
        }

        // S = Q @ K^T (logits already in log2 domain)
        const uint32_t kbase = sb + (KOFF + (kt & 1) * KSTG) * 4;
        float s[8][4] = {};
        #pragma unroll
        for (int kk = 0; kk < 8; kk++) {
            #pragma unroll
            for (int ntp = 0; ntp < 4; ntp++) {
                uint32_t kb4[4];
                ldsm4(kb4, kbase + (ntp * 16 * KSR + kk * 8 + kfrag) * 4);
                mma_tf32(s[2*ntp    ], qf[kk], kb4);
                mma_tf32(s[2*ntp + 1], qf[kk], kb4 + 2);
            }
        }

        // online softmax via ex2; P stays in registers
        {
            float mx0 = -1e30f, mx1 = -1e30f;
            #pragma unroll
            for (int nt = 0; nt < 8; nt++) {
                mx0 = fmaxf(mx0, fmaxf(s[nt][0], s[nt][1]));
                mx1 = fmaxf(mx1, fmaxf(s[nt][2], s[nt][3]));
            }
            #pragma unroll
            for (int off = 1; off < 4; off <<= 1) {
                mx0 = fmaxf(mx0, __shfl_xor_sync(0xffffffffu, mx0, off));
                mx1 = fmaxf(mx1, __shfl_xor_sync(0xffffffffu, mx1, off));
            }
            const float mn0 = fmaxf(m0r, mx0), mn1 = fmaxf(m1r, mx1);
            const float al0 = ex2f(m0r - mn0), al1 = ex2f(m1r - mn1);
            float rs0 = 0.f, rs1 = 0.f;
            #pragma unroll
            for (int nt = 0; nt < 8; nt++) {
                float p0 = ex2f(s[nt][0] - mn0);
                float p1 = ex2f(s[nt][1] - mn0);
                float p2 = ex2f(s[nt][2] - mn1);
                float p3 = ex2f(s[nt][3] - mn1);
                rs0 += p0 + p1;  rs1 += p2 + p3;
                s[nt][0] = __uint_as_float(f2tf(p0));
                s[nt][1] = __uint_as_float(f2tf(p1));
                s[nt][2] = __uint_as_float(f2tf(p2));
                s[nt][3] = __uint_as_float(f2tf(p3));
            }
            #pragma unroll
            for (int off = 1; off < 4; off <<= 1) {
                rs0 += __shfl_xor_sync(0xffffffffu, rs0, off);
                rs1 += __shfl_xor_sync(0xffffffffu, rs1, off);
            }
            l0 = l0 * al0 + rs0;  m0r = mn0;
            l1 = l1 * al1 + rs1;  m1r = mn1;
            #pragma unroll
            for (int nt = 0; nt < 8; nt++) {
                o[nt][0] *= al0;  o[nt][1] *= al0;
                o[nt][2] *= al1;  o[nt][3] *= al1;
            }
        }

        // O += P @ V (V rows permuted to match C-frag register order)
        const uint32_t* Vu = (uint32_t*)fsm + VOFF + (kt & 1) * KSTG;
        #pragma unroll
        for (int kk = 0; kk < 8; kk++) {
            uint32_t vb[8][2];
            #pragma unroll
            for (int nt = 0; nt < 8; nt++) {
                vb[nt][0] = Vu[(kk * 8 + 2 * tig    ) * VSR + nt * 8 + gid];
                vb[nt][1] = Vu[(kk * 8 + 2 * tig + 1) * VSR + nt * 8 + gid];
            }
            uint32_t a[4];
            a[0] = __float_as_uint(s[kk][0]);
            a[1] = __float_as_uint(s[kk][2]);
            a[2] = __float_as_uint(s[kk][1]);
            a[3] = __float_as_uint(s[kk][3]);
            #pragma unroll
            for (int nt = 0; nt < 8; nt++)
                mma_tf32(o[nt], a, vb[nt]);
        }

        if (kt < 15) {
            CP_WAIT(0);
            __syncthreads();
        }
    }

    // write O (normalized, tf32-rounded) into concat layout [B,S,E]
    const int bb = bh / NH, hh = bh % NH;
    {
        const float inv0 = 1.0f / l0, inv1 = 1.0f / l1;
        const int r0 = qt * 128 + w * 16 + gid;
        const int r1 = r0 + 8;
        #pragma unroll
        for (int nt = 0; nt < 8; nt++) {
            const int col = hh * ND + nt * 8 + 2 * tig;
            float2 w0 = { __uint_as_float(f2tf(o[nt][0] * inv0)),
                          __uint_as_float(f2tf(o[nt][1] * inv0)) };
            float2 w1 = { __uint_as_float(f2tf(o[nt][2] * inv1)),
                          __uint_as_float(f2tf(o[nt][3] * inv1)) };
            *(float2*)(g_attn + ((size_t)bb * NS + r0) * NE + col) = w0;
            *(float2*)(g_attn + ((size_t)bb * NS + r1) * NE + col) = w1;
        }
    }
}

// ---------------------------------------------------------------------------
extern "C" void kernel_launch(void* const* d_in, const int* in_sizes, int n_in,
                              void* d_out, int out_size)
{
    const float* X  = (const float*)d_in[0];
    const float* Wq = (const float*)d_in[1];
    const float* bq = (const float*)d_in[2];
    const float* Wk = (const float*)d_in[3];
    const float* bk = (const float*)d_in[4];
    const float* Wv = (const float*)d_in[5];
    const float* bv = (const float*)d_in[6];
    const float* Wo = (const float*)d_in[7];
    const float* bo = (const float*)d_in[8];
    float* out = (float*)d_out;

    cudaFuncSetAttribute(gemm_kernel,
                         cudaFuncAttributeMaxDynamicSharedMemorySize, GEMM_SMEM);
    cudaFuncSetAttribute(flash_kernel,
                         cudaFuncAttributeMaxDynamicSharedMemorySize, FLASH_SMEM);

    const int nround = (NX4 + 4 * NW4 + 255) / 256;   // 8448 blocks
    round_kernel<<<nround, 256>>>(X, Wq, Wk, Wv, Wo);

    gemm_kernel<<<dim3(NT/128, NE/128, 3), 256, GEMM_SMEM>>>(
        bq, bk, bv, nullptr, 0);

    flash_kernel<<<dim3(NS/128, NB*NH), 256, FLASH_SMEM>>>();

    gemm_kernel<<<dim3(NT/128, NE/128, 1), 256, GEMM_SMEM>>>(
        bo, bo, bo, out, 1);
}

// round 10
// speedup vs baseline: 2.2598x; 1.7587x over previous
#include <cuda_runtime.h>
#include <cuda_fp16.h>
#include <cstdint>

#define NB 8
#define NS 1024
#define NE 768
#define NH 12
#define ND 64
#define NT (NB*NS)   // 8192 tokens

// Scratch (device globals: allocation-free rule). All fp16 intermediates.
__device__ __half g_q[NB*NH*NS*ND];    // [B,H,S,D], Q pre-scaled by log2e/8
__device__ __half g_k[NB*NH*NS*ND];
__device__ __half g_v[NB*NH*NS*ND];
__device__ __half g_attn[NT*NE];       // [B,S,E]
__device__ __half g_xh[NT*NE];         // fp16 X
__device__ __half g_wh[4*NE*NE];       // fp16 W^T: [w][n][k]

// ---------------------------------------------------------------------------
__device__ __forceinline__ uint32_t pack_h2(float lo, float hi) {
    uint32_t d;
    asm("cvt.rn.f16x2.f32 %0, %1, %2;" : "=r"(d) : "f"(hi), "f"(lo));
    return d;
}
__device__ __forceinline__ float ex2f(float x) {
    float r;
    asm("ex2.approx.ftz.f32 %0, %1;" : "=f"(r) : "f"(x));
    return r;
}
// D += A*B  (m16n8k16 fp16 in, f32 accumulate)
__device__ __forceinline__ void mma_f16(float* d, const uint32_t* a, const uint32_t* b) {
    asm volatile(
        "mma.sync.aligned.m16n8k16.row.col.f32.f16.f16.f32 "
        "{%0,%1,%2,%3}, {%4,%5,%6,%7}, {%8,%9}, {%0,%1,%2,%3};"
        : "+f"(d[0]), "+f"(d[1]), "+f"(d[2]), "+f"(d[3])
        : "r"(a[0]), "r"(a[1]), "r"(a[2]), "r"(a[3]), "r"(b[0]), "r"(b[1]));
}
__device__ __forceinline__ void ldsm4(uint32_t* r, uint32_t addr) {
    asm volatile("ldmatrix.sync.aligned.m8n8.x4.shared.b16 {%0,%1,%2,%3}, [%4];"
        : "=r"(r[0]), "=r"(r[1]), "=r"(r[2]), "=r"(r[3]) : "r"(addr));
}
__device__ __forceinline__ void ldsm4t(uint32_t* r, uint32_t addr) {
    asm volatile("ldmatrix.sync.aligned.m8n8.x4.trans.shared.b16 {%0,%1,%2,%3}, [%4];"
        : "=r"(r[0]), "=r"(r[1]), "=r"(r[2]), "=r"(r[3]) : "r"(addr));
}
__device__ __forceinline__ uint32_t smem_u32(const void* p) {
    uint32_t a;
    asm("{ .reg .u64 t; cvta.to.shared.u64 t, %1; cvt.u32.u64 %0, t; }"
        : "=r"(a) : "l"(p));
    return a;
}
__device__ __forceinline__ void cp16(uint32_t dst, const void* src) {
    asm volatile("cp.async.cg.shared.global [%0], [%1], 16;"
                 :: "r"(dst), "l"(src) : "memory");
}
#define CP_COMMIT() asm volatile("cp.async.commit_group;" ::: "memory")
#define CP_WAIT(n)  asm volatile("cp.async.wait_group %0;" :: "n"(n) : "memory")

// ---------------------------------------------------------------------------
// Kernel 0a: X -> fp16 (8 floats / thread)
// ---------------------------------------------------------------------------
__global__ __launch_bounds__(256) void convert_x_kernel(const float* __restrict__ X)
{
    int idx = blockIdx.x * 256 + threadIdx.x;          // over NT*NE/8
    float4 a = ((const float4*)X)[2*idx];
    float4 b = ((const float4*)X)[2*idx+1];
    uint4 o = { pack_h2(a.x, a.y), pack_h2(a.z, a.w),
                pack_h2(b.x, b.y), pack_h2(b.z, b.w) };
    ((uint4*)g_xh)[idx] = o;
}

// ---------------------------------------------------------------------------
// Kernel 0b: W [k][n] f32 -> g_wh [n][k] fp16 (transpose + convert)
// ---------------------------------------------------------------------------
__global__ __launch_bounds__(256) void transpose_w_kernel(
    const float* __restrict__ Wq, const float* __restrict__ Wk,
    const float* __restrict__ Wv, const float* __restrict__ Wo)
{
    const int w = blockIdx.z;
    const float* src = (w == 0) ? Wq : (w == 1) ? Wk : (w == 2) ? Wv : Wo;
    __half* dst = g_wh + (size_t)w * NE * NE;

    __shared__ float t[32][33];
    int x = blockIdx.x * 32 + threadIdx.x;   // n
    int y = blockIdx.y * 32 + threadIdx.y;   // k
    #pragma unroll
    for (int j = 0; j < 32; j += 8)
        t[threadIdx.y + j][threadIdx.x] = src[(size_t)(y + j) * NE + x];
    __syncthreads();
    x = blockIdx.y * 32 + threadIdx.x;       // k
    y = blockIdx.x * 32 + threadIdx.y;       // n
    #pragma unroll
    for (int j = 0; j < 32; j += 8)
        dst[(size_t)(y + j) * NE + x] = __float2half_rn(t[threadIdx.x][threadIdx.y + j]);
}

// ---------------------------------------------------------------------------
// GEMM fp16: D[8192 x 768] = A @ W + bias. BM=128 BN=128 BK=64, m16n8k16,
// 3-stage cp.async, ldmatrix A+B frags, 2 CTAs/SM. 8 warps = 4m x 2n.
// mode 0: z picks Wq/Wk/Wv -> g_q/g_k/g_v fp16 (Q scaled log2e/8).
// mode 1: Wo, A = g_attn -> f32 Dext + bias (final output).
// ---------------------------------------------------------------------------
#define GSTR 72                 // halfs per smem row (144B, ldmatrix conflict-free)
#define AST (128*GSTR)          // 9216 halfs per stage
#define GEMM_SMEM (6*AST*2)     // 110592 B  (3 A stages + 3 B stages)
#define QSCALE 0.18033688011112042f   // 0.125 * log2(e)

__global__ __launch_bounds__(256, 2) void gemm_kernel(
    const float* __restrict__ b0_, const float* __restrict__ b1_,
    const float* __restrict__ b2_,
    float* __restrict__ Dext, int mode)
{
    extern __shared__ __half gsm[];
    const uint32_t ua = smem_u32(gsm);             // A stages: [3][AST]
    const uint32_t ub = ua + 3 * AST * 2;          // B stages: [3][AST]

    const int z = blockIdx.z;
    const __half* A = (mode == 0) ? g_xh : g_attn;
    const __half* Wt = g_wh + (size_t)((mode == 0) ? z : 3) * NE * NE;
    const float* bias = (mode == 0) ? (z == 0 ? b0_ : z == 1 ? b1_ : b2_) : b0_;
    __half* Dh = (z == 0) ? g_q : (z == 1) ? g_k : g_v;
    const float qs = (mode == 0 && z == 0) ? QSCALE : 1.0f;

    const int tid = threadIdx.x, wid = tid >> 5, lane = tid & 31;
    const int gid = lane >> 2, tig = lane & 3;
    const int wm = wid >> 1, wn = wid & 1;
    const int m0 = blockIdx.x * 128, n0 = blockIdx.y * 128;

    // staging: A 128x64h (8 chunks/row), B 128x64h. 4 chunks each per thread.
    int rr[4], cc8[4];
    #pragma unroll
    for (int i = 0; i < 4; i++) {
        int idx = tid + i * 256;
        rr[i] = idx >> 3;  cc8[i] = (idx & 7) * 8;
    }

    // ldmatrix lane geometry
    const int arow  = lane & 15;                       // A/Q rows
    const int acol  = (lane >> 4) * 8;                 // k half-offset
    const int nrow  = (lane & 7) + ((lane >> 4) << 3); // B n-rows
    const int koff  = ((lane >> 3) & 1) * 8;           // B k half-offset
    uint32_t a_base[2];
    #pragma unroll
    for (int mi = 0; mi < 2; mi++)
        a_base[mi] = (uint32_t)((wm * 32 + mi * 16 + arow) * GSTR + acol);

    // prologue: stages 0, 1
    #pragma unroll
    for (int s = 0; s < 2; s++) {
        #pragma unroll
        for (int i = 0; i < 4; i++) {
            cp16(ua + (s * AST + rr[i] * GSTR + cc8[i]) * 2,
                 A + (size_t)(m0 + rr[i]) * NE + s * 64 + cc8[i]);
            cp16(ub + (s * AST + rr[i] * GSTR + cc8[i]) * 2,
                 Wt + (size_t)(n0 + rr[i]) * NE + s * 64 + cc8[i]);
        }
        CP_COMMIT();
    }
    CP_WAIT(1);
    __syncthreads();

    float c[2][8][4] = {};

    int cur = 0;
    #pragma unroll 1
    for (int kb = 0; kb < 12; kb++) {
        if (kb < 10) {
            const int sl = (cur + 2) % 3;
            const int kn = (kb + 2) * 64;
            #pragma unroll
            for (int i = 0; i < 4; i++) {
                cp16(ua + (sl * AST + rr[i] * GSTR + cc8[i]) * 2,
                     A + (size_t)(m0 + rr[i]) * NE + kn + cc8[i]);
                cp16(ub + (sl * AST + rr[i] * GSTR + cc8[i]) * 2,
                     Wt + (size_t)(n0 + rr[i]) * NE + kn + cc8[i]);
            }
            CP_COMMIT();
        }

        const uint32_t a_st = ua + (cur * AST) * 2;
        const uint32_t b_st = ub + (cur * AST) * 2;
        #pragma unroll
        for (int kk = 0; kk < 4; kk++) {
            uint32_t a[2][4];
            ldsm4(a[0], a_st + (a_base[0] + kk * 16) * 2);
            ldsm4(a[1], a_st + (a_base[1] + kk * 16) * 2);
            #pragma unroll
            for (int ntp = 0; ntp < 4; ntp++) {
                uint32_t b4[4];
                ldsm4(b4, b_st + ((wn * 64 + ntp * 16 + nrow) * GSTR + kk * 16 + koff) * 2);
                mma_f16(c[0][2*ntp    ], a[0], b4);
                mma_f16(c[0][2*ntp + 1], a[0], b4 + 2);
                mma_f16(c[1][2*ntp    ], a[1], b4);
                mma_f16(c[1][2*ntp + 1], a[1], b4 + 2);
            }
        }

        if (kb < 11) {
            if (kb < 10) { CP_WAIT(1); } else { CP_WAIT(0); }
            __syncthreads();
        }
        cur = (cur == 2) ? 0 : cur + 1;
    }

    #pragma unroll
    for (int mi = 0; mi < 2; mi++) {
        const int r0 = m0 + wm * 32 + mi * 16 + gid;
        #pragma unroll
        for (int nt = 0; nt < 8; nt++) {
            const int n = n0 + wn * 64 + nt * 8 + 2 * tig;
            const float bx = bias[n], by = bias[n + 1];
            if (mode == 0) {
                uint32_t lo = pack_h2((c[mi][nt][0] + bx) * qs, (c[mi][nt][1] + by) * qs);
                uint32_t hi = pack_h2((c[mi][nt][2] + bx) * qs, (c[mi][nt][3] + by) * qs);
                const int h = n >> 6, d = n & 63;
                const int b0i = r0 >> 10, s0 = r0 & 1023;
                const int b1i = (r0 + 8) >> 10, s1 = (r0 + 8) & 1023;
                *(uint32_t*)(Dh + (((size_t)b0i * NH + h) * NS + s0) * ND + d) = lo;
                *(uint32_t*)(Dh + (((size_t)b1i * NH + h) * NS + s1) * ND + d) = hi;
            } else {
                float2 lo = { c[mi][nt][0] + bx, c[mi][nt][1] + by };
                float2 hi = { c[mi][nt][2] + bx, c[mi][nt][3] + by };
                *(float2*)(Dext + (size_t)r0 * NE + n) = lo;
                *(float2*)(Dext + (size_t)(r0 + 8) * NE + n) = hi;
            }
        }
    }
}

// ---------------------------------------------------------------------------
// Flash attention fp16: 256 threads / 8 warps, 16 Q-rows per warp, m16n8k16.
// P in registers (C-frag -> fp16 A-frag pack, V via ldmatrix.trans).
// K/V double-buffered, one barrier/kt, ex2 softmax (Q pre-scaled log2e/8).
// grid=(8, 96). smem 55296 B -> 2 CTAs/SM.
// ---------------------------------------------------------------------------
#define FQS 72
#define KOFFH (128*FQS)            // halfs: Q region
#define VOFFH (KOFFH + 2*64*FQS)
#define KSTGH (64*FQS)
#define FLASH_SMEM ((VOFFH + 2*64*FQS) * 2)   // 55296 B

__global__ __launch_bounds__(256, 2) void flash_kernel()
{
    extern __shared__ __half fsm[];
    const uint32_t sb = smem_u32(fsm);

    const int qt = blockIdx.x, bh = blockIdx.y;
    const __half* Qg = g_q + (size_t)bh * NS * ND + qt * 128 * ND;
    const __half* Kg = g_k + (size_t)bh * NS * ND;
    const __half* Vg = g_v + (size_t)bh * NS * ND;

    const int tid = threadIdx.x, w = tid >> 5, lane = tid & 31;
    const int gid = lane >> 2, tig = lane & 3;

    const int arow = lane & 15;
    const int acol = (lane >> 4) * 8;
    const int nrow = (lane & 7) + ((lane >> 4) << 3);
    const int koff = ((lane >> 3) & 1) * 8;
    const int vrow = (lane & 7) + (((lane >> 3) & 1) << 3);
    const int vcol = (lane >> 4) * 8;

    // stage Q (128x64h) + K0 + V0 (64x64h each)
    #pragma unroll
    for (int i = 0; i < 4; i++) {
        int idx = tid + i * 256, r = idx >> 3, c8 = (idx & 7) * 8;
        cp16(sb + (r * FQS + c8) * 2, Qg + r * 64 + c8);
    }
    #pragma unroll
    for (int i = 0; i < 2; i++) {
        int idx = tid + i * 256, r = idx >> 3, c8 = (idx & 7) * 8;
        cp16(sb + (KOFFH + r * FQS + c8) * 2, Kg + r * 64 + c8);
        cp16(sb + (VOFFH + r * FQS + c8) * 2, Vg + r * 64 + c8);
    }
    CP_COMMIT();
    CP_WAIT(0);
    __syncthreads();

    // hoist Q fragments (16 rows per warp): 4 k-steps x 4 regs
    uint32_t qf[4][4];
    #pragma unroll
    for (int kk = 0; kk < 4; kk++)
        ldsm4(qf[kk], sb + ((w * 16 + arow) * FQS + kk * 16 + acol) * 2);

    float o[8][4] = {};
    float m0r = -1e30f, m1r = -1e30f, l0 = 0.f, l1 = 0.f;

    #pragma unroll 1
    for (int kt = 0; kt < 16; kt++) {
        if (kt < 15) {
            const int sl = (kt + 1) & 1;
            const __half* kg = Kg + (size_t)(kt + 1) * 64 * 64;
            const __half* vg = Vg + (size_t)(kt + 1) * 64 * 64;
            #pragma unroll
            for (int i = 0; i < 2; i++) {
                int idx = tid + i * 256, r = idx >> 3, c8 = (idx & 7) * 8;
                cp16(sb + (KOFFH + sl * KSTGH + r * FQS + c8) * 2, kg + r * 64 + c8);
                cp16(sb + (VOFFH + sl * KSTGH + r * FQS + c8) * 2, vg + r * 64 + c8);
            }
            CP_COMMIT();
        }

        // S = Q @ K^T (log2-domain logits)
        const uint32_t kbase = sb + (KOFFH + (kt & 1) * KSTGH) * 2;
        float s[8][4] = {};
        #pragma unroll
        for (int kk = 0; kk < 4; kk++) {
            #pragma unroll
            for (int ntp = 0; ntp < 4; ntp++) {
                uint32_t b4[4];
                ldsm4(b4, kbase + ((ntp * 16 + nrow) * FQS + kk * 16 + koff) * 2);
                mma_f16(s[2*ntp    ], qf[kk], b4);
                mma_f16(s[2*ntp + 1], qf[kk], b4 + 2);
            }
        }

        // online softmax via ex2
        {
            float mx0 = -1e30f, mx1 = -1e30f;
            #pragma unroll
            for (int nt = 0; nt < 8; nt++) {
                mx0 = fmaxf(mx0, fmaxf(s[nt][0], s[nt][1]));
                mx1 = fmaxf(mx1, fmaxf(s[nt][2], s[nt][3]));
            }
            #pragma unroll
            for (int off = 1; off < 4; off <<= 1) {
                mx0 = fmaxf(mx0, __shfl_xor_sync(0xffffffffu, mx0, off));
                mx1 = fmaxf(mx1, __shfl_xor_sync(0xffffffffu, mx1, off));
            }
            const float mn0 = fmaxf(m0r, mx0), mn1 = fmaxf(m1r, mx1);
            const float al0 = ex2f(m0r - mn0), al1 = ex2f(m1r - mn1);
            float rs0 = 0.f, rs1 = 0.f;
            #pragma unroll
            for (int nt = 0; nt < 8; nt++) {
                s[nt][0] = ex2f(s[nt][0] - mn0);
                s[nt][1] = ex2f(s[nt][1] - mn0);
                s[nt][2] = ex2f(s[nt][2] - mn1);
                s[nt][3] = ex2f(s[nt][3] - mn1);
                rs0 += s[nt][0] + s[nt][1];
                rs1 += s[nt][2] + s[nt][3];
            }
            #pragma unroll
            for (int off = 1; off < 4; off <<= 1) {
                rs0 += __shfl_xor_sync(0xffffffffu, rs0, off);
                rs1 += __shfl_xor_sync(0xffffffffu, rs1, off);
            }
            l0 = l0 * al0 + rs0;  m0r = mn0;
            l1 = l1 * al1 + rs1;  m1r = mn1;
            #pragma unroll
            for (int nt = 0; nt < 8; nt++) {
                o[nt][0] *= al0;  o[nt][1] *= al0;
                o[nt][2] *= al1;  o[nt][3] *= al1;
            }
        }

        // O += P @ V  (P packed to fp16 A-frags; V via ldmatrix.trans)
        const uint32_t vbase = sb + (VOFFH + (kt & 1) * KSTGH) * 2;
        #pragma unroll
        for (int kk = 0; kk < 4; kk++) {
            uint32_t a[4];
            a[0] = pack_h2(s[2*kk    ][0], s[2*kk    ][1]);
            a[1] = pack_h2(s[2*kk    ][2], s[2*kk    ][3]);
            a[2] = pack_h2(s[2*kk + 1][0], s[2*kk + 1][1]);
            a[3] = pack_h2(s[2*kk + 1][2], s[2*kk + 1][3]);
            #pragma unroll
            for (int ntp = 0; ntp < 4; ntp++) {
                uint32_t v4[4];
                ldsm4t(v4, vbase + ((kk * 16 + vrow) * FQS + ntp * 16 + vcol) * 2);
                mma_f16(o[2*ntp    ], a, v4);
                mma_f16(o[2*ntp + 1], a, v4 + 2);
            }
        }

        if (kt < 15) {
            CP_WAIT(0);
            __syncthreads();
        }
    }

    // write O (normalized) as fp16 into concat layout [B,S,E]
    const int bb = bh / NH, hh = bh % NH;
    {
        const float inv0 = 1.0f / l0, inv1 = 1.0f / l1;
        const int r0 = qt * 128 + w * 16 + gid;
        const int r1 = r0 + 8;
        #pragma unroll
        for (int nt = 0; nt < 8; nt++) {
            const int col = hh * ND + nt * 8 + 2 * tig;
            uint32_t w0 = pack_h2(o[nt][0] * inv0, o[nt][1] * inv0);
            uint32_t w1 = pack_h2(o[nt][2] * inv1, o[nt][3] * inv1);
            *(uint32_t*)(g_attn + ((size_t)bb * NS + r0) * NE + col) = w0;
            *(uint32_t*)(g_attn + ((size_t)bb * NS + r1) * NE + col) = w1;
        }
    }
}

// ---------------------------------------------------------------------------
extern "C" void kernel_launch(void* const* d_in, const int* in_sizes, int n_in,
                              void* d_out, int out_size)
{
    const float* X  = (const float*)d_in[0];
    const float* Wq = (const float*)d_in[1];
    const float* bq = (const float*)d_in[2];
    const float* Wk = (const float*)d_in[3];
    const float* bk = (const float*)d_in[4];
    const float* Wv = (const float*)d_in[5];
    const float* bv = (const float*)d_in[6];
    const float* Wo = (const float*)d_in[7];
    const float* bo = (const float*)d_in[8];
    float* out = (float*)d_out;

    cudaFuncSetAttribute(gemm_kernel,
                         cudaFuncAttributeMaxDynamicSharedMemorySize, GEMM_SMEM);
    cudaFuncSetAttribute(flash_kernel,
                         cudaFuncAttributeMaxDynamicSharedMemorySize, FLASH_SMEM);

    convert_x_kernel<<<NT*NE/8/256, 256>>>(X);
    transpose_w_kernel<<<dim3(24, 24, 4), dim3(32, 8)>>>(Wq, Wk, Wv, Wo);

    gemm_kernel<<<dim3(NT/128, NE/128, 3), 256, GEMM_SMEM>>>(
        bq, bk, bv, nullptr, 0);

    flash_kernel<<<dim3(NS/128, NB*NH), 256, FLASH_SMEM>>>();

    gemm_kernel<<<dim3(NT/128, NE/128, 1), 256, GEMM_SMEM>>>(
        bo, bo, bo, out, 1);
}